// round 12
// baseline (speedup 1.0000x reference)
#include <cuda_runtime.h>
#include <cuda_fp16.h>

// ---------------------------------------------------------------------------
// MLP-Mixer on tensor cores, round 11: single-pass fp16 (C = Ah @ Bh), now
// 256 threads / 8 warps / TWO elements per warp (16 elems/CTA, grid 512).
// Each weight fragment LDS.128 feeds 8 MMAs (4 m-tiles x 2 kt) -> weight LDS
// bytes+instructions per element halve; per-warp MMA ILP doubles so
// 2 warps/SMSP still hides LDS latency. Hidden loop re-chunked to 8x32 to
// keep dAcc transient (32 regs/element). half2 epilogue, fragment-swizzled
// weights, w2 pre-scaled by 1/6.
// ---------------------------------------------------------------------------

#define MIX_EPS 1e-5f
#define NTHREADS 256
#define NWARPS 8

// ---- SMEM byte offsets (same as R10) ----
#define OFF_H     0         // 16 * 32*34 * 4 = 69632
#define OFF_ST    69632     // 16 * 64 * 4 = 4096
#define OFF_B1T   73728     // 256 f
#define OFF_B1C   74752
#define OFF_B2T   75776     // 32 f
#define OFF_B2C   75904
#define OFF_LN1G  76032
#define OFF_LN1B  76160
#define OFF_LN2G  76288
#define OFF_LN2B  76416
#define OFF_WT    76544     // weight region (also fp32 staging for pre/head)
#define OFF_W1T   76544     // 256 rows * 32 halves * 2B = 16384
#define OFF_W1C   92928     // 16384
#define OFF_W2T   109312    // 32 rows * 288 halves * 2B = 18432
#define OFF_W2C   127744    // 18432
#define SMEM_BYTES 146176

__device__ __forceinline__ float2 ffma2(float2 a, float2 b, float2 c) {
    unsigned long long au = *reinterpret_cast<unsigned long long*>(&a);
    unsigned long long bu = *reinterpret_cast<unsigned long long*>(&b);
    unsigned long long cu = *reinterpret_cast<unsigned long long*>(&c);
    unsigned long long du;
    asm("fma.rn.f32x2 %0, %1, %2, %3;" : "=l"(du) : "l"(au), "l"(bu), "l"(cu));
    return *reinterpret_cast<float2*>(&du);
}
__device__ __forceinline__ float2 fadd2(float2 a, float2 b) {
    unsigned long long au = *reinterpret_cast<unsigned long long*>(&a);
    unsigned long long bu = *reinterpret_cast<unsigned long long*>(&b);
    unsigned long long du;
    asm("add.rn.f32x2 %0, %1, %2;" : "=l"(du) : "l"(au), "l"(bu));
    return *reinterpret_cast<float2*>(&du);
}

__device__ __forceinline__ void mma16816(float d[4], const unsigned a[4],
                                         unsigned b0, unsigned b1) {
    asm volatile(
        "mma.sync.aligned.m16n8k16.row.col.f32.f16.f16.f32 "
        "{%0,%1,%2,%3}, {%4,%5,%6,%7}, {%8,%9}, {%0,%1,%2,%3};\n"
        : "+f"(d[0]), "+f"(d[1]), "+f"(d[2]), "+f"(d[3])
        : "r"(a[0]), "r"(a[1]), "r"(a[2]), "r"(a[3]), "r"(b0), "r"(b1));
}

// hswish (without 1/6) on two packed fp16 values.
__device__ __forceinline__ __half2 hswish2(__half2 v) {
    const __half2 three = __floats2half2_rn(3.f, 3.f);
    const __half2 six   = __floats2half2_rn(6.f, 6.f);
    const __half2 zero  = __floats2half2_rn(0.f, 0.f);
    __half2 c = __hmin2(__hmax2(__hadd2(v, three), zero), six);
    return __hmul2(v, c);
}

// Weight layout identical to R10:
//   w1: row n (256), 32 halves packed; group tg at halves tg*8 holds
//       [kt0 frag (4 halves) | kt1 frag (4 halves)]. One LDS.128/(ch,nt).
//   w2: row n (32), stride 288 halves; group (pair,tg) at halves
//       (pair*4+tg)*8, pair = ktile>>1; [even-ktile frag | odd-ktile frag].
// w2 pre-scaled by 1/6.
template <bool TOKEN>
__device__ __forceinline__ void mix_branch_mma(
    float* h0, float* h1, float* st0, float* st1,
    const __half* w1, const __half* w2,
    const float* b1, const float* b2,
    const float* g, const float* bb, int lane)
{
    const int gid = lane >> 2;
    const int tg  = lane & 3;

    // ---- LN stats for both elements (lane = row) ----
    float s0 = 0.f, q0 = 0.f, s1 = 0.f, q1 = 0.f;
    #pragma unroll
    for (int j = 0; j < 32; j += 2) {
        float2 v = *reinterpret_cast<const float2*>(h0 + lane * 34 + j);
        s0 += v.x + v.y; q0 += v.x * v.x + v.y * v.y;
        float2 w = *reinterpret_cast<const float2*>(h1 + lane * 34 + j);
        s1 += w.x + w.y; q1 += w.x * w.x + w.y * w.y;
    }
    float m0 = s0 * 0.03125f, m1 = s1 * 0.03125f;
    float r0 = rsqrtf(fmaxf(q0 * 0.03125f - m0 * m0, 0.f) + MIX_EPS);
    float r1 = rsqrtf(fmaxf(q1 * 0.03125f - m1 * m1, 0.f) + MIX_EPS);
    st0[lane] = m0; st0[32 + lane] = r0;
    st1[lane] = m1; st1[32 + lane] = r1;
    __syncwarp();

    // ---- A1 fragments for both elements: a1[elem][mt][kt][4] ----
    unsigned a1[2][2][2][4];
    #pragma unroll
    for (int e = 0; e < 2; e++) {
        float* h  = e ? h1 : h0;
        float* st = e ? st1 : st0;
        #pragma unroll
        for (int mt = 0; mt < 2; mt++)
        #pragma unroll
        for (int kt = 0; kt < 2; kt++) {
            #pragma unroll
            for (int rr = 0; rr < 2; rr++) {
                int am = mt * 16 + gid + rr * 8;
                #pragma unroll
                for (int cc = 0; cc < 2; cc++) {
                    int ak = kt * 16 + tg * 2 + cc * 8;
                    float v0, v1;
                    if (TOKEN) {
                        float x0 = h[ak * 34 + am];
                        float x1 = h[(ak + 1) * 34 + am];
                        float gm = g[am], bm = bb[am];
                        v0 = (x0 - st[ak]) * st[32 + ak] * gm + bm;
                        v1 = (x1 - st[ak + 1]) * st[32 + ak + 1] * gm + bm;
                    } else {
                        float2 x = *reinterpret_cast<const float2*>(h + am * 34 + ak);
                        float mm = st[am], ri = st[32 + am];
                        v0 = (x.x - mm) * ri * g[ak] + bb[ak];
                        v1 = (x.y - mm) * ri * g[ak + 1] + bb[ak + 1];
                    }
                    __half2 hv = __floats2half2_rn(v0, v1);
                    a1[e][mt][kt][rr + cc * 2] = *reinterpret_cast<unsigned*>(&hv);
                }
            }
        }
    }

    // ---- out accumulators [elem][mt][ntO][4], init with bias b2 ----
    float outacc[2][2][4][4];
    #pragma unroll
    for (int ntO = 0; ntO < 4; ntO++) {
        int c = ntO * 8 + tg * 2;
        float bv0 = b2[c], bv1 = b2[c + 1];
        #pragma unroll
        for (int e = 0; e < 2; e++)
        #pragma unroll
        for (int mt = 0; mt < 2; mt++) {
            outacc[e][mt][ntO][0] = bv0; outacc[e][mt][ntO][1] = bv1;
            outacc[e][mt][ntO][2] = bv0; outacc[e][mt][ntO][3] = bv1;
        }
    }

    // ---- hidden loop over DIM=256 in 8 chunks of 32 ----
    #pragma unroll 1
    for (int ch = 0; ch < 8; ch++) {
        // shared w1 fragments for this chunk (one LDS.128 per nt, feeds 8 MMAs)
        uint4 fw1[4];
        #pragma unroll
        for (int nt = 0; nt < 4; nt++) {
            int n = ch * 32 + nt * 8 + gid;
            fw1[nt] = *reinterpret_cast<const uint4*>(w1 + n * 32 + tg * 8);
        }

        // gemm1 + epilogue per element -> a2[elem][kt2][mt][4]
        unsigned a2[2][2][2][4];
        #pragma unroll
        for (int e = 0; e < 2; e++) {
            float dAcc[2][4][4];
            #pragma unroll
            for (int nt = 0; nt < 4; nt++) {
                float2 bv = *reinterpret_cast<const float2*>(
                    b1 + ch * 32 + nt * 8 + tg * 2);
                #pragma unroll
                for (int mt = 0; mt < 2; mt++) {
                    dAcc[mt][nt][0] = bv.x; dAcc[mt][nt][1] = bv.y;
                    dAcc[mt][nt][2] = bv.x; dAcc[mt][nt][3] = bv.y;
                }
            }
            #pragma unroll
            for (int nt = 0; nt < 4; nt++) {
                mma16816(dAcc[0][nt], a1[e][0][0], fw1[nt].x, fw1[nt].y);
                mma16816(dAcc[1][nt], a1[e][1][0], fw1[nt].x, fw1[nt].y);
                mma16816(dAcc[0][nt], a1[e][0][1], fw1[nt].z, fw1[nt].w);
                mma16816(dAcc[1][nt], a1[e][1][1], fw1[nt].z, fw1[nt].w);
            }
            #pragma unroll
            for (int kt2 = 0; kt2 < 2; kt2++)
            #pragma unroll
            for (int part = 0; part < 2; part++) {
                int nt = kt2 * 2 + part;
                #pragma unroll
                for (int mt = 0; mt < 2; mt++) {
                    __half2 ha = __floats2half2_rn(dAcc[mt][nt][0],
                                                   dAcc[mt][nt][1]);
                    __half2 hb = __floats2half2_rn(dAcc[mt][nt][2],
                                                   dAcc[mt][nt][3]);
                    __half2 ra = hswish2(ha);
                    __half2 rb = hswish2(hb);
                    a2[e][kt2][mt][part * 2 + 0] = *reinterpret_cast<unsigned*>(&ra);
                    a2[e][kt2][mt][part * 2 + 1] = *reinterpret_cast<unsigned*>(&rb);
                }
            }
        }

        // gemm2: chunk ch == ktile pair; one LDS.128 per ntO serves both
        // elements and both kt2 tiles (8 MMAs per load)
        #pragma unroll
        for (int ntO = 0; ntO < 4; ntO++) {
            int n = ntO * 8 + gid;
            uint4 f = *reinterpret_cast<const uint4*>(
                w2 + n * 288 + (ch * 4 + tg) * 8);
            #pragma unroll
            for (int e = 0; e < 2; e++) {
                mma16816(outacc[e][0][ntO], a2[e][0][0], f.x, f.y);
                mma16816(outacc[e][1][ntO], a2[e][0][1], f.x, f.y);
                mma16816(outacc[e][0][ntO], a2[e][1][0], f.z, f.w);
                mma16816(outacc[e][1][ntO], a2[e][1][1], f.z, f.w);
            }
        }
    }

    // ---- residual add back into h ----
    #pragma unroll
    for (int e = 0; e < 2; e++) {
        float* h = e ? h1 : h0;
        if (TOKEN) {
            #pragma unroll
            for (int mt = 0; mt < 2; mt++)
            #pragma unroll
            for (int ntO = 0; ntO < 4; ntO++) {
                int mm = mt * 16 + gid;
                int nn = ntO * 8 + tg * 2;
                h[nn * 34 + mm]           += outacc[e][mt][ntO][0];
                h[(nn + 1) * 34 + mm]     += outacc[e][mt][ntO][1];
                h[nn * 34 + mm + 8]       += outacc[e][mt][ntO][2];
                h[(nn + 1) * 34 + mm + 8] += outacc[e][mt][ntO][3];
            }
        } else {
            #pragma unroll
            for (int mt = 0; mt < 2; mt++)
            #pragma unroll
            for (int ntO = 0; ntO < 4; ntO++) {
                int rr0 = mt * 16 + gid;
                int c = ntO * 8 + tg * 2;
                float2* p0 = reinterpret_cast<float2*>(h + rr0 * 34 + c);
                float2 v0 = *p0;
                v0.x += outacc[e][mt][ntO][0]; v0.y += outacc[e][mt][ntO][1];
                *p0 = v0;
                float2* p1 = reinterpret_cast<float2*>(h + (rr0 + 8) * 34 + c);
                float2 v1 = *p1;
                v1.x += outacc[e][mt][ntO][2]; v1.y += outacc[e][mt][ntO][3];
                *p1 = v1;
            }
        }
    }
    __syncwarp();
}

extern __shared__ char smem_raw[];

__global__ __launch_bounds__(NTHREADS, 1)
void mixer_kernel(
    const float* __restrict__ x,
    const float* __restrict__ conv_w, const float* __restrict__ conv_b,
    const float* __restrict__ fc0_w,  const float* __restrict__ fc0_b,
    const float* __restrict__ ln1_g,  const float* __restrict__ ln1_b,
    const float* __restrict__ w11,    const float* __restrict__ b11,
    const float* __restrict__ w12,    const float* __restrict__ b12,
    const float* __restrict__ ln2_g,  const float* __restrict__ ln2_b,
    const float* __restrict__ w21,    const float* __restrict__ b21,
    const float* __restrict__ w22,    const float* __restrict__ b22,
    const float* __restrict__ fc1_w,  const float* __restrict__ fc1_b,
    const float* __restrict__ fcout_w,const float* __restrict__ fcout_b,
    float* __restrict__ out, int B)
{
    const int tid = threadIdx.x;
    const int lane = tid & 31;
    const int wid = tid >> 5;      // 0..7, two elements per warp

    float* sH   = reinterpret_cast<float*>(smem_raw + OFF_H);
    float* sSt  = reinterpret_cast<float*>(smem_raw + OFF_ST);
    float* sB1t = reinterpret_cast<float*>(smem_raw + OFF_B1T);
    float* sB1c = reinterpret_cast<float*>(smem_raw + OFF_B1C);
    float* sB2t = reinterpret_cast<float*>(smem_raw + OFF_B2T);
    float* sB2c = reinterpret_cast<float*>(smem_raw + OFF_B2C);
    float* sL1g = reinterpret_cast<float*>(smem_raw + OFF_LN1G);
    float* sL1b = reinterpret_cast<float*>(smem_raw + OFF_LN1B);
    float* sL2g = reinterpret_cast<float*>(smem_raw + OFF_LN2G);
    float* sL2b = reinterpret_cast<float*>(smem_raw + OFF_LN2B);
    __half* w1t = reinterpret_cast<__half*>(smem_raw + OFF_W1T);
    __half* w1c = reinterpret_cast<__half*>(smem_raw + OFF_W1C);
    __half* w2t = reinterpret_cast<__half*>(smem_raw + OFF_W2T);
    __half* w2c = reinterpret_cast<__half*>(smem_raw + OFF_W2C);
    float* sFw = reinterpret_cast<float*>(smem_raw + OFF_WT);
    float* sFo = reinterpret_cast<float*>(smem_raw + OFF_W1C);

    const int e0 = blockIdx.x * 16 + wid * 2;
    const int e1 = e0 + 1;
    const bool act0 = (e0 < B), act1 = (e1 < B);
    float* h0 = sH + (wid * 2) * (32 * 34);
    float* h1 = h0 + 32 * 34;
    float* st0 = sSt + wid * 128;
    float* st1 = st0 + 64;

    // ---- stage fc0 weights, preprocess (conv1x1 + fc0) ----
    for (int i = tid; i < 1024; i += NTHREADS) sFw[i] = fc0_w[i];
    if (tid < 32) sB1t[tid] = fc0_b[tid];
    __syncthreads();

    {
        const float cw0 = conv_w[0], cw1 = conv_w[1], cw2 = conv_w[2];
        const float cb  = conv_b[0];
        #pragma unroll
        for (int e = 0; e < 2; e++) {
            const int eb = e0 + e;
            if (eb >= B) break;
            float* hh = e ? h1 : h0;
            const float* xb = x + (size_t)eb * 3072 + lane * 32;
            float2 gp[16];
            #pragma unroll
            for (int qq = 0; qq < 8; qq++) {
                float4 v0 = *reinterpret_cast<const float4*>(xb + qq * 4);
                float4 v1 = *reinterpret_cast<const float4*>(xb + 1024 + qq * 4);
                float4 v2 = *reinterpret_cast<const float4*>(xb + 2048 + qq * 4);
                gp[2 * qq]     = make_float2(cw0 * v0.x + cw1 * v1.x + cw2 * v2.x + cb,
                                             cw0 * v0.y + cw1 * v1.y + cw2 * v2.y + cb);
                gp[2 * qq + 1] = make_float2(cw0 * v0.z + cw1 * v1.z + cw2 * v2.z + cb,
                                             cw0 * v0.w + cw1 * v1.w + cw2 * v2.w + cb);
            }
            for (int j = 0; j < 32; j++) {
                const float4* wq = reinterpret_cast<const float4*>(sFw + j * 32);
                float2 acc = make_float2(0.f, 0.f), accb = make_float2(0.f, 0.f);
                #pragma unroll
                for (int qq = 0; qq < 8; qq++) {
                    float4 w = wq[qq];
                    acc  = ffma2(gp[2 * qq],     make_float2(w.x, w.y), acc);
                    accb = ffma2(gp[2 * qq + 1], make_float2(w.z, w.w), accb);
                }
                float2 sv = fadd2(acc, accb);
                hh[lane * 34 + j] = sv.x + sv.y + sB1t[j];
            }
        }
    }
    __syncthreads();

    // ---- 8 layers x 2 repeats ----
    for (int l = 0; l < 8; l++) {
        // stage fp16 fragment-swizzled weight planes for this layer
        {
            const float* g11 = w11 + l * 8192;
            const float* g21 = w21 + l * 8192;
            for (int i = tid; i < 8192; i += NTHREADS) {
                int d = i >> 5, k = i & 31;
                int kt = k >> 4, rrr = k & 15;
                int tgp, pos;
                if (rrr < 8) { tgp = rrr >> 1; pos = rrr & 1; }
                else         { tgp = (rrr - 8) >> 1; pos = 2 + (rrr & 1); }
                int idx = d * 32 + tgp * 8 + kt * 4 + pos;
                w1t[idx] = __float2half_rn(g11[i]);
                w1c[idx] = __float2half_rn(g21[i]);
            }
            const float* g12 = w12 + l * 8192;
            const float* g22 = w22 + l * 8192;
            for (int i = tid; i < 8192; i += NTHREADS) {
                int n = i >> 8, k = i & 255;
                int ktile = k >> 4, rrr = k & 15;
                int tgp, pos;
                if (rrr < 8) { tgp = rrr >> 1; pos = rrr & 1; }
                else         { tgp = (rrr - 8) >> 1; pos = 2 + (rrr & 1); }
                int idx = n * 288 + ((ktile >> 1) * 4 + tgp) * 8
                          + (ktile & 1) * 4 + pos;
                w2t[idx] = __float2half_rn(g12[i] * (1.0f / 6.0f));
                w2c[idx] = __float2half_rn(g22[i] * (1.0f / 6.0f));
            }
            if (tid < 256) { sB1t[tid] = b11[l * 256 + tid]; sB1c[tid] = b21[l * 256 + tid]; }
            if (tid < 32) {
                sB2t[tid] = b12[l * 32 + tid];
                sB2c[tid] = b22[l * 32 + tid];
                sL1g[tid] = ln1_g[l * 32 + tid];
                sL1b[tid] = ln1_b[l * 32 + tid];
                sL2g[tid] = ln2_g[l * 32 + tid];
                sL2b[tid] = ln2_b[l * 32 + tid];
            }
        }
        __syncthreads();

        for (int rep = 0; rep < 2; rep++) {
            mix_branch_mma<true >(h0, h1, st0, st1, w1t, w2t,
                                  sB1t, sB2t, sL1g, sL1b, lane);
            mix_branch_mma<false>(h0, h1, st0, st1, w1c, w2c,
                                  sB1c, sB2c, sL2g, sL2b, lane);
        }
        __syncthreads();
    }

    // ---- head: fc1 + hardswish + avgpool(32) + fcout ----
    {
        const float4* s1 = reinterpret_cast<const float4*>(fc1_w);
        float4* d1 = reinterpret_cast<float4*>(sFw);
        for (int i = tid; i < 1024; i += NTHREADS) d1[i] = s1[i];
        for (int i = tid; i < 1280; i += NTHREADS) sFo[i] = fcout_w[i];
        if (tid < 128) sB1t[tid] = fc1_b[tid];
        if (tid < 10)  sB2t[tid] = fcout_b[tid];
    }
    __syncthreads();

    #pragma unroll
    for (int e = 0; e < 2; e++) {
        const bool act = e ? act1 : act0;
        if (!act) break;
        float* hh = e ? h1 : h0;
        float2 ap[16];
        #pragma unroll
        for (int t = 0; t < 16; t++)
            ap[t] = *reinterpret_cast<const float2*>(hh + lane * 34 + 2 * t);
        float pool[4] = {0.f, 0.f, 0.f, 0.f};
        for (int d = 0; d < 128; d++) {
            const float4* wq = reinterpret_cast<const float4*>(sFw + d * 32);
            float2 acc = make_float2(0.f, 0.f), accb = make_float2(0.f, 0.f);
            #pragma unroll
            for (int qq = 0; qq < 8; qq++) {
                float4 w = wq[qq];
                acc  = ffma2(ap[2 * qq],     make_float2(w.x, w.y), acc);
                accb = ffma2(ap[2 * qq + 1], make_float2(w.z, w.w), accb);
            }
            float2 sv = fadd2(acc, accb);
            float v = sv.x + sv.y + sB1t[d];
            float y = v * fminf(fmaxf(v + 3.0f, 0.0f), 6.0f) * (1.0f / 6.0f);
            pool[d >> 5] += y;
        }
        #pragma unroll
        for (int p = 0; p < 4; p++) pool[p] *= (1.0f / 32.0f);
        const int eb = e ? e1 : e0;
        #pragma unroll
        for (int o = 0; o < 10; o++) {
            float4 wv = *reinterpret_cast<const float4*>(sFo + o * 128 + lane * 4);
            float v = pool[0] * wv.x + pool[1] * wv.y + pool[2] * wv.z + pool[3] * wv.w;
            #pragma unroll
            for (int sft = 16; sft > 0; sft >>= 1)
                v += __shfl_xor_sync(0xffffffffu, v, sft);
            if (lane == 0) out[(size_t)eb * 10 + o] = v + sB2t[o];
        }
    }
}

extern "C" void kernel_launch(void* const* d_in, const int* in_sizes, int n_in,
                              void* d_out, int out_size) {
    const float* x       = (const float*)d_in[0];
    const float* conv_w  = (const float*)d_in[1];
    const float* conv_b  = (const float*)d_in[2];
    const float* fc0_w   = (const float*)d_in[3];
    const float* fc0_b   = (const float*)d_in[4];
    const float* ln1_g   = (const float*)d_in[5];
    const float* ln1_b   = (const float*)d_in[6];
    const float* w11     = (const float*)d_in[7];
    const float* b11     = (const float*)d_in[8];
    const float* w12     = (const float*)d_in[9];
    const float* b12     = (const float*)d_in[10];
    const float* ln2_g   = (const float*)d_in[11];
    const float* ln2_b   = (const float*)d_in[12];
    const float* w21     = (const float*)d_in[13];
    const float* b21     = (const float*)d_in[14];
    const float* w22     = (const float*)d_in[15];
    const float* b22     = (const float*)d_in[16];
    const float* fc1_w   = (const float*)d_in[17];
    const float* fc1_b   = (const float*)d_in[18];
    const float* fcout_w = (const float*)d_in[19];
    const float* fcout_b = (const float*)d_in[20];
    float* out = (float*)d_out;

    const int B = in_sizes[0] / 3072;
    const int blocks = (B + 15) / 16;

    cudaFuncSetAttribute(mixer_kernel,
                         cudaFuncAttributeMaxDynamicSharedMemorySize,
                         SMEM_BYTES);
    mixer_kernel<<<blocks, NTHREADS, SMEM_BYTES>>>(
        x, conv_w, conv_b, fc0_w, fc0_b, ln1_g, ln1_b,
        w11, b11, w12, b12, ln2_g, ln2_b, w21, b21, w22, b22,
        fc1_w, fc1_b, fcout_w, fcout_b, out, B);
}

// round 13
// speedup vs baseline: 1.2201x; 1.2201x over previous
#include <cuda_runtime.h>
#include <cuda_fp16.h>

// ---------------------------------------------------------------------------
// MLP-Mixer on tensor cores, round 12: identical per-warp math to R10 (the
// 1252us best: single-pass fp16 C = Ah @ Bh, LDS.128 fragment weights, half2
// epilogue) but split into TWO 8-warp CTAs per SM (8 elems/CTA, SMEM 109.3KB,
// __launch_bounds__(256,2)). Same 16 warps/SM, but independent barrier
// domains: while one CTA stages weights / sits at __syncthreads, the other
// CTA's warps fill the issue slots.
// ---------------------------------------------------------------------------

#define MIX_EPS 1e-5f
#define NTHREADS 256
#define NWARPS 8

// ---- SMEM byte offsets ----
#define OFF_H     0         // 8 * 32*34 * 4 = 34816
#define OFF_ST    34816     // 8 * 64 * 4 = 2048
#define OFF_B1T   36864     // 256 f
#define OFF_B1C   37888
#define OFF_B2T   38912     // 32 f
#define OFF_B2C   39040
#define OFF_LN1G  39168
#define OFF_LN1B  39296
#define OFF_LN2G  39424
#define OFF_LN2B  39552
#define OFF_WT    39680     // weight region (also fp32 staging for pre/head)
#define OFF_W1T   39680     // 256 rows * 32 halves * 2B = 16384
#define OFF_W1C   56064     // 16384
#define OFF_W2T   72448     // 32 rows * 288 halves * 2B = 18432
#define OFF_W2C   90880     // 18432
#define SMEM_BYTES 109312   // 2 CTAs/SM: 218624 <= 228KB carveout

__device__ __forceinline__ float2 ffma2(float2 a, float2 b, float2 c) {
    unsigned long long au = *reinterpret_cast<unsigned long long*>(&a);
    unsigned long long bu = *reinterpret_cast<unsigned long long*>(&b);
    unsigned long long cu = *reinterpret_cast<unsigned long long*>(&c);
    unsigned long long du;
    asm("fma.rn.f32x2 %0, %1, %2, %3;" : "=l"(du) : "l"(au), "l"(bu), "l"(cu));
    return *reinterpret_cast<float2*>(&du);
}
__device__ __forceinline__ float2 fadd2(float2 a, float2 b) {
    unsigned long long au = *reinterpret_cast<unsigned long long*>(&a);
    unsigned long long bu = *reinterpret_cast<unsigned long long*>(&b);
    unsigned long long du;
    asm("add.rn.f32x2 %0, %1, %2;" : "=l"(du) : "l"(au), "l"(bu));
    return *reinterpret_cast<float2*>(&du);
}

__device__ __forceinline__ void mma16816(float d[4], const unsigned a[4],
                                         unsigned b0, unsigned b1) {
    asm volatile(
        "mma.sync.aligned.m16n8k16.row.col.f32.f16.f16.f32 "
        "{%0,%1,%2,%3}, {%4,%5,%6,%7}, {%8,%9}, {%0,%1,%2,%3};\n"
        : "+f"(d[0]), "+f"(d[1]), "+f"(d[2]), "+f"(d[3])
        : "r"(a[0]), "r"(a[1]), "r"(a[2]), "r"(a[3]), "r"(b0), "r"(b1));
}

// hswish (without 1/6) on two packed fp16 values.
__device__ __forceinline__ __half2 hswish2(__half2 v) {
    const __half2 three = __floats2half2_rn(3.f, 3.f);
    const __half2 six   = __floats2half2_rn(6.f, 6.f);
    const __half2 zero  = __floats2half2_rn(0.f, 0.f);
    __half2 c = __hmin2(__hmax2(__hadd2(v, three), zero), six);
    return __hmul2(v, c);
}

// Fragment-swizzled weight layout (single fp16 plane):
//   w1: row n (256 rows), 32 halves packed. Group tg (0..3) at halves tg*8:
//       [kt0 frag: k(2tg),k(2tg+1),k(2tg+8),k(2tg+9) | kt1 frag: +16 each].
//       One LDS.128 per (nc,nt) -> both kt fragments -> 4 MMAs.
//   w2: row n (32 rows), stride 288 halves (144 words = 16 mod 32). Group
//       (pair,tg) at halves (pair*4+tg)*8, pair = ktile>>1; within group
//       [even-ktile frag | odd-ktile frag]. One LDS.128 per (j,ntO) -> 2 kt2.
// w2 pre-scaled by 1/6.
template <bool TOKEN>
__device__ __forceinline__ void mix_branch_mma(
    float* h, float* st,
    const __half* w1, const __half* w2,
    const float* b1, const float* b2,
    const float* g, const float* bb, int lane)
{
    const int gid = lane >> 2;
    const int tg  = lane & 3;

    // ---- LN stats (lane = row) ----
    float s = 0.f, q = 0.f;
    #pragma unroll
    for (int j = 0; j < 32; j += 2) {
        float2 v = *reinterpret_cast<const float2*>(h + lane * 34 + j);
        s += v.x + v.y; q += v.x * v.x + v.y * v.y;
    }
    float m = s * 0.03125f;
    float r = rsqrtf(fmaxf(q * 0.03125f - m * m, 0.f) + MIX_EPS);
    st[lane] = m; st[32 + lane] = r;
    __syncwarp();

    // ---- A1 fragments (LN output, fp16) ----
    unsigned a1[2][2][4];
    #pragma unroll
    for (int mt = 0; mt < 2; mt++)
    #pragma unroll
    for (int kt = 0; kt < 2; kt++) {
        #pragma unroll
        for (int rr = 0; rr < 2; rr++) {
            int am = mt * 16 + gid + rr * 8;
            #pragma unroll
            for (int cc = 0; cc < 2; cc++) {
                int ak = kt * 16 + tg * 2 + cc * 8;
                float v0, v1;
                if (TOKEN) {
                    float x0 = h[ak * 34 + am];
                    float x1 = h[(ak + 1) * 34 + am];
                    float gm = g[am], bm = bb[am];
                    v0 = (x0 - st[ak]) * st[32 + ak] * gm + bm;
                    v1 = (x1 - st[ak + 1]) * st[32 + ak + 1] * gm + bm;
                } else {
                    float2 x = *reinterpret_cast<const float2*>(h + am * 34 + ak);
                    float mm = st[am], ri = st[32 + am];
                    v0 = (x.x - mm) * ri * g[ak] + bb[ak];
                    v1 = (x.y - mm) * ri * g[ak + 1] + bb[ak + 1];
                }
                __half2 hv = __floats2half2_rn(v0, v1);
                a1[mt][kt][rr + cc * 2] = *reinterpret_cast<unsigned*>(&hv);
            }
        }
    }

    // ---- out accumulators, init with bias b2 ----
    float outacc[2][4][4];
    #pragma unroll
    for (int ntO = 0; ntO < 4; ntO++) {
        int c = ntO * 8 + tg * 2;
        float bv0 = b2[c], bv1 = b2[c + 1];
        #pragma unroll
        for (int mt = 0; mt < 2; mt++) {
            outacc[mt][ntO][0] = bv0; outacc[mt][ntO][1] = bv1;
            outacc[mt][ntO][2] = bv0; outacc[mt][ntO][3] = bv1;
        }
    }

    // ---- hidden loop over DIM=256 in 4 chunks of 64 ----
    for (int nc = 0; nc < 4; nc++) {
        // dAcc init with b1 bias (per hidden column)
        float dAcc[2][8][4];
        #pragma unroll
        for (int nt = 0; nt < 8; nt++) {
            float2 bv = *reinterpret_cast<const float2*>(
                b1 + nc * 64 + nt * 8 + tg * 2);
            #pragma unroll
            for (int mt = 0; mt < 2; mt++) {
                dAcc[mt][nt][0] = bv.x; dAcc[mt][nt][1] = bv.y;
                dAcc[mt][nt][2] = bv.x; dAcc[mt][nt][3] = bv.y;
            }
        }

        // gemm1: per nt one LDS.128 (both kt fragments) -> 4 MMAs
        #pragma unroll
        for (int nt = 0; nt < 8; nt++) {
            int n = nc * 64 + nt * 8 + gid;
            uint4 f = *reinterpret_cast<const uint4*>(w1 + n * 32 + tg * 8);
            mma16816(dAcc[0][nt], a1[0][0], f.x, f.y);
            mma16816(dAcc[1][nt], a1[1][0], f.x, f.y);
            mma16816(dAcc[0][nt], a1[0][1], f.z, f.w);
            mma16816(dAcc[1][nt], a1[1][1], f.z, f.w);
        }

        // epilogue + gemm2: j indexes kt2 pairs; one LDS.128 per (j,ntO)
        #pragma unroll
        for (int j = 0; j < 2; j++) {
            uint4 fw[4];
            #pragma unroll
            for (int ntO = 0; ntO < 4; ntO++) {
                int n = ntO * 8 + gid;
                fw[ntO] = *reinterpret_cast<const uint4*>(
                    w2 + n * 288 + ((nc * 2 + j) * 4 + tg) * 8);
            }
            #pragma unroll
            for (int p = 0; p < 2; p++) {
                int kt2 = 2 * j + p;
                unsigned a2[2][4];
                #pragma unroll
                for (int part = 0; part < 2; part++) {
                    int nt = 2 * kt2 + part;
                    #pragma unroll
                    for (int mt = 0; mt < 2; mt++) {
                        __half2 ha = __floats2half2_rn(dAcc[mt][nt][0],
                                                       dAcc[mt][nt][1]);
                        __half2 hb = __floats2half2_rn(dAcc[mt][nt][2],
                                                       dAcc[mt][nt][3]);
                        __half2 ra = hswish2(ha);
                        __half2 rb = hswish2(hb);
                        a2[mt][part * 2 + 0] = *reinterpret_cast<unsigned*>(&ra);
                        a2[mt][part * 2 + 1] = *reinterpret_cast<unsigned*>(&rb);
                    }
                }
                #pragma unroll
                for (int ntO = 0; ntO < 4; ntO++) {
                    unsigned b0 = p ? fw[ntO].z : fw[ntO].x;
                    unsigned b1r = p ? fw[ntO].w : fw[ntO].y;
                    mma16816(outacc[0][ntO], a2[0], b0, b1r);
                    mma16816(outacc[1][ntO], a2[1], b0, b1r);
                }
            }
        }
    }

    // ---- residual add back into h ----
    if (TOKEN) {
        #pragma unroll
        for (int mt = 0; mt < 2; mt++)
        #pragma unroll
        for (int ntO = 0; ntO < 4; ntO++) {
            int mm = mt * 16 + gid;
            int nn = ntO * 8 + tg * 2;
            h[nn * 34 + mm]           += outacc[mt][ntO][0];
            h[(nn + 1) * 34 + mm]     += outacc[mt][ntO][1];
            h[nn * 34 + mm + 8]       += outacc[mt][ntO][2];
            h[(nn + 1) * 34 + mm + 8] += outacc[mt][ntO][3];
        }
    } else {
        #pragma unroll
        for (int mt = 0; mt < 2; mt++)
        #pragma unroll
        for (int ntO = 0; ntO < 4; ntO++) {
            int rr0 = mt * 16 + gid;
            int c = ntO * 8 + tg * 2;
            float2* p0 = reinterpret_cast<float2*>(h + rr0 * 34 + c);
            float2 v0 = *p0;
            v0.x += outacc[mt][ntO][0]; v0.y += outacc[mt][ntO][1];
            *p0 = v0;
            float2* p1 = reinterpret_cast<float2*>(h + (rr0 + 8) * 34 + c);
            float2 v1 = *p1;
            v1.x += outacc[mt][ntO][2]; v1.y += outacc[mt][ntO][3];
            *p1 = v1;
        }
    }
    __syncwarp();
}

extern __shared__ char smem_raw[];

__global__ __launch_bounds__(NTHREADS, 2)
void mixer_kernel(
    const float* __restrict__ x,
    const float* __restrict__ conv_w, const float* __restrict__ conv_b,
    const float* __restrict__ fc0_w,  const float* __restrict__ fc0_b,
    const float* __restrict__ ln1_g,  const float* __restrict__ ln1_b,
    const float* __restrict__ w11,    const float* __restrict__ b11,
    const float* __restrict__ w12,    const float* __restrict__ b12,
    const float* __restrict__ ln2_g,  const float* __restrict__ ln2_b,
    const float* __restrict__ w21,    const float* __restrict__ b21,
    const float* __restrict__ w22,    const float* __restrict__ b22,
    const float* __restrict__ fc1_w,  const float* __restrict__ fc1_b,
    const float* __restrict__ fcout_w,const float* __restrict__ fcout_b,
    float* __restrict__ out, int B)
{
    const int tid = threadIdx.x;
    const int lane = tid & 31;
    const int wid = tid >> 5;      // 0..7, one element per warp

    float* sH   = reinterpret_cast<float*>(smem_raw + OFF_H);
    float* sSt  = reinterpret_cast<float*>(smem_raw + OFF_ST);
    float* sB1t = reinterpret_cast<float*>(smem_raw + OFF_B1T);
    float* sB1c = reinterpret_cast<float*>(smem_raw + OFF_B1C);
    float* sB2t = reinterpret_cast<float*>(smem_raw + OFF_B2T);
    float* sB2c = reinterpret_cast<float*>(smem_raw + OFF_B2C);
    float* sL1g = reinterpret_cast<float*>(smem_raw + OFF_LN1G);
    float* sL1b = reinterpret_cast<float*>(smem_raw + OFF_LN1B);
    float* sL2g = reinterpret_cast<float*>(smem_raw + OFF_LN2G);
    float* sL2b = reinterpret_cast<float*>(smem_raw + OFF_LN2B);
    __half* w1t = reinterpret_cast<__half*>(smem_raw + OFF_W1T);
    __half* w1c = reinterpret_cast<__half*>(smem_raw + OFF_W1C);
    __half* w2t = reinterpret_cast<__half*>(smem_raw + OFF_W2T);
    __half* w2c = reinterpret_cast<__half*>(smem_raw + OFF_W2C);
    float* sFw = reinterpret_cast<float*>(smem_raw + OFF_WT);
    float* sFo = reinterpret_cast<float*>(smem_raw + OFF_W1C);

    const int eb = blockIdx.x * NWARPS + wid;
    const bool act = (eb < B);
    float* h  = sH + wid * (32 * 34);
    float* st = sSt + wid * 64;

    // ---- stage fc0 weights, preprocess (conv1x1 + fc0) ----
    for (int i = tid; i < 1024; i += NTHREADS) sFw[i] = fc0_w[i];
    if (tid < 32) sB1t[tid] = fc0_b[tid];
    __syncthreads();

    if (act) {
        const float cw0 = conv_w[0], cw1 = conv_w[1], cw2 = conv_w[2];
        const float cb  = conv_b[0];
        const float* xb = x + (size_t)eb * 3072 + lane * 32;
        float2 gp[16];
        #pragma unroll
        for (int qq = 0; qq < 8; qq++) {
            float4 v0 = *reinterpret_cast<const float4*>(xb + qq * 4);
            float4 v1 = *reinterpret_cast<const float4*>(xb + 1024 + qq * 4);
            float4 v2 = *reinterpret_cast<const float4*>(xb + 2048 + qq * 4);
            gp[2 * qq]     = make_float2(cw0 * v0.x + cw1 * v1.x + cw2 * v2.x + cb,
                                         cw0 * v0.y + cw1 * v1.y + cw2 * v2.y + cb);
            gp[2 * qq + 1] = make_float2(cw0 * v0.z + cw1 * v1.z + cw2 * v2.z + cb,
                                         cw0 * v0.w + cw1 * v1.w + cw2 * v2.w + cb);
        }
        for (int j = 0; j < 32; j++) {
            const float4* wq = reinterpret_cast<const float4*>(sFw + j * 32);
            float2 acc = make_float2(0.f, 0.f), accb = make_float2(0.f, 0.f);
            #pragma unroll
            for (int qq = 0; qq < 8; qq++) {
                float4 w = wq[qq];
                acc  = ffma2(gp[2 * qq],     make_float2(w.x, w.y), acc);
                accb = ffma2(gp[2 * qq + 1], make_float2(w.z, w.w), accb);
            }
            float2 sv = fadd2(acc, accb);
            h[lane * 34 + j] = sv.x + sv.y + sB1t[j];
        }
    }
    __syncthreads();

    // ---- 8 layers x 2 repeats ----
    for (int l = 0; l < 8; l++) {
        // stage fp16 fragment-swizzled weight planes for this layer
        {
            const float* g11 = w11 + l * 8192;
            const float* g21 = w21 + l * 8192;
            for (int i = tid; i < 8192; i += NTHREADS) {
                int d = i >> 5, k = i & 31;
                int kt = k >> 4, rrr = k & 15;
                int tgp, pos;
                if (rrr < 8) { tgp = rrr >> 1; pos = rrr & 1; }
                else         { tgp = (rrr - 8) >> 1; pos = 2 + (rrr & 1); }
                int idx = d * 32 + tgp * 8 + kt * 4 + pos;
                w1t[idx] = __float2half_rn(g11[i]);
                w1c[idx] = __float2half_rn(g21[i]);
            }
            const float* g12 = w12 + l * 8192;
            const float* g22 = w22 + l * 8192;
            for (int i = tid; i < 8192; i += NTHREADS) {
                int n = i >> 8, k = i & 255;
                int ktile = k >> 4, rrr = k & 15;
                int tgp, pos;
                if (rrr < 8) { tgp = rrr >> 1; pos = rrr & 1; }
                else         { tgp = (rrr - 8) >> 1; pos = 2 + (rrr & 1); }
                int idx = n * 288 + ((ktile >> 1) * 4 + tgp) * 8
                          + (ktile & 1) * 4 + pos;
                w2t[idx] = __float2half_rn(g12[i] * (1.0f / 6.0f));
                w2c[idx] = __float2half_rn(g22[i] * (1.0f / 6.0f));
            }
            if (tid < 256) { sB1t[tid] = b11[l * 256 + tid]; sB1c[tid] = b21[l * 256 + tid]; }
            if (tid < 32) {
                sB2t[tid] = b12[l * 32 + tid];
                sB2c[tid] = b22[l * 32 + tid];
                sL1g[tid] = ln1_g[l * 32 + tid];
                sL1b[tid] = ln1_b[l * 32 + tid];
                sL2g[tid] = ln2_g[l * 32 + tid];
                sL2b[tid] = ln2_b[l * 32 + tid];
            }
        }
        __syncthreads();

        if (act) {
            for (int rep = 0; rep < 2; rep++) {
                mix_branch_mma<true >(h, st, w1t, w2t, sB1t, sB2t, sL1g, sL1b, lane);
                mix_branch_mma<false>(h, st, w1c, w2c, sB1c, sB2c, sL2g, sL2b, lane);
            }
        }
        __syncthreads();
    }

    // ---- head: fc1 + hardswish + avgpool(32) + fcout ----
    {
        const float4* s1 = reinterpret_cast<const float4*>(fc1_w);
        float4* d1 = reinterpret_cast<float4*>(sFw);
        for (int i = tid; i < 1024; i += NTHREADS) d1[i] = s1[i];
        for (int i = tid; i < 1280; i += NTHREADS) sFo[i] = fcout_w[i];
        if (tid < 128) sB1t[tid] = fc1_b[tid];
        if (tid < 10)  sB2t[tid] = fcout_b[tid];
    }
    __syncthreads();

    if (act) {
        float2 ap[16];
        #pragma unroll
        for (int t = 0; t < 16; t++)
            ap[t] = *reinterpret_cast<const float2*>(h + lane * 34 + 2 * t);
        float pool[4] = {0.f, 0.f, 0.f, 0.f};
        for (int d = 0; d < 128; d++) {
            const float4* wq = reinterpret_cast<const float4*>(sFw + d * 32);
            float2 acc = make_float2(0.f, 0.f), accb = make_float2(0.f, 0.f);
            #pragma unroll
            for (int qq = 0; qq < 8; qq++) {
                float4 w = wq[qq];
                acc  = ffma2(ap[2 * qq],     make_float2(w.x, w.y), acc);
                accb = ffma2(ap[2 * qq + 1], make_float2(w.z, w.w), accb);
            }
            float2 sv = fadd2(acc, accb);
            float v = sv.x + sv.y + sB1t[d];
            float y = v * fminf(fmaxf(v + 3.0f, 0.0f), 6.0f) * (1.0f / 6.0f);
            pool[d >> 5] += y;
        }
        #pragma unroll
        for (int p = 0; p < 4; p++) pool[p] *= (1.0f / 32.0f);
        #pragma unroll
        for (int o = 0; o < 10; o++) {
            float4 wv = *reinterpret_cast<const float4*>(sFo + o * 128 + lane * 4);
            float v = pool[0] * wv.x + pool[1] * wv.y + pool[2] * wv.z + pool[3] * wv.w;
            #pragma unroll
            for (int sft = 16; sft > 0; sft >>= 1)
                v += __shfl_xor_sync(0xffffffffu, v, sft);
            if (lane == 0) out[(size_t)eb * 10 + o] = v + sB2t[o];
        }
    }
}

extern "C" void kernel_launch(void* const* d_in, const int* in_sizes, int n_in,
                              void* d_out, int out_size) {
    const float* x       = (const float*)d_in[0];
    const float* conv_w  = (const float*)d_in[1];
    const float* conv_b  = (const float*)d_in[2];
    const float* fc0_w   = (const float*)d_in[3];
    const float* fc0_b   = (const float*)d_in[4];
    const float* ln1_g   = (const float*)d_in[5];
    const float* ln1_b   = (const float*)d_in[6];
    const float* w11     = (const float*)d_in[7];
    const float* b11     = (const float*)d_in[8];
    const float* w12     = (const float*)d_in[9];
    const float* b12     = (const float*)d_in[10];
    const float* ln2_g   = (const float*)d_in[11];
    const float* ln2_b   = (const float*)d_in[12];
    const float* w21     = (const float*)d_in[13];
    const float* b21     = (const float*)d_in[14];
    const float* w22     = (const float*)d_in[15];
    const float* b22     = (const float*)d_in[16];
    const float* fc1_w   = (const float*)d_in[17];
    const float* fc1_b   = (const float*)d_in[18];
    const float* fcout_w = (const float*)d_in[19];
    const float* fcout_b = (const float*)d_in[20];
    float* out = (float*)d_out;

    const int B = in_sizes[0] / 3072;
    const int blocks = (B + NWARPS - 1) / NWARPS;

    cudaFuncSetAttribute(mixer_kernel,
                         cudaFuncAttributeMaxDynamicSharedMemorySize,
                         SMEM_BYTES);
    mixer_kernel<<<blocks, NTHREADS, SMEM_BYTES>>>(
        x, conv_w, conv_b, fc0_w, fc0_b, ln1_g, ln1_b,
        w11, b11, w12, b12, ln2_g, ln2_b, w21, b21, w22, b22,
        fc1_w, fc1_b, fcout_w, fcout_b, out, B);
}

// round 14
// speedup vs baseline: 1.2820x; 1.0507x over previous
#include <cuda_runtime.h>
#include <cuda_fp16.h>

// ---------------------------------------------------------------------------
// MLP-Mixer on tensor cores, round 13: R12 (two 8-warp CTAs/SM, single-pass
// fp16 C = Ah @ Bh, LDS.128 fragment weights, half2 epilogue) + weight
// conversion HOISTED into a one-shot prep kernel writing fragment-swizzled
// fp16 planes to __device__ globals. Main-kernel staging is now a pure
// LDG.128->STS.128 copy (17 uint4/thread/layer) instead of 2x8192 scalar
// convert+scatter iterations (~1/3 of the old instruction stream, and the
// dominant L1-wavefront source).
// ---------------------------------------------------------------------------

#define MIX_EPS 1e-5f
#define NTHREADS 256
#define NWARPS 8

// ---- converted-weight globals (fragment-swizzled fp16 planes) ----
// w1 plane: 256 rows * 32 halves; w2 plane: 32 rows * 288 halves.
__device__ __half gW1[8][2][256 * 32];
__device__ __half gW2[8][2][32 * 288];

// ---- SMEM byte offsets ----
#define OFF_H     0         // 8 * 32*34 * 4 = 34816
#define OFF_ST    34816     // 8 * 64 * 4 = 2048
#define OFF_B1T   36864     // 256 f
#define OFF_B1C   37888
#define OFF_B2T   38912     // 32 f
#define OFF_B2C   39040
#define OFF_LN1G  39168
#define OFF_LN1B  39296
#define OFF_LN2G  39424
#define OFF_LN2B  39552
#define OFF_WT    39680     // weight region (also fp32 staging for pre/head)
#define OFF_W1T   39680     // 16384
#define OFF_W1C   56064     // 16384
#define OFF_W2T   72448     // 18432
#define OFF_W2C   90880     // 18432
#define SMEM_BYTES 109312   // 2 CTAs/SM

__device__ __forceinline__ float2 ffma2(float2 a, float2 b, float2 c) {
    unsigned long long au = *reinterpret_cast<unsigned long long*>(&a);
    unsigned long long bu = *reinterpret_cast<unsigned long long*>(&b);
    unsigned long long cu = *reinterpret_cast<unsigned long long*>(&c);
    unsigned long long du;
    asm("fma.rn.f32x2 %0, %1, %2, %3;" : "=l"(du) : "l"(au), "l"(bu), "l"(cu));
    return *reinterpret_cast<float2*>(&du);
}
__device__ __forceinline__ float2 fadd2(float2 a, float2 b) {
    unsigned long long au = *reinterpret_cast<unsigned long long*>(&a);
    unsigned long long bu = *reinterpret_cast<unsigned long long*>(&b);
    unsigned long long du;
    asm("add.rn.f32x2 %0, %1, %2;" : "=l"(du) : "l"(au), "l"(bu));
    return *reinterpret_cast<float2*>(&du);
}

__device__ __forceinline__ void mma16816(float d[4], const unsigned a[4],
                                         unsigned b0, unsigned b1) {
    asm volatile(
        "mma.sync.aligned.m16n8k16.row.col.f32.f16.f16.f32 "
        "{%0,%1,%2,%3}, {%4,%5,%6,%7}, {%8,%9}, {%0,%1,%2,%3};\n"
        : "+f"(d[0]), "+f"(d[1]), "+f"(d[2]), "+f"(d[3])
        : "r"(a[0]), "r"(a[1]), "r"(a[2]), "r"(a[3]), "r"(b0), "r"(b1));
}

__device__ __forceinline__ __half2 hswish2(__half2 v) {
    const __half2 three = __floats2half2_rn(3.f, 3.f);
    const __half2 six   = __floats2half2_rn(6.f, 6.f);
    const __half2 zero  = __floats2half2_rn(0.f, 0.f);
    __half2 c = __hmin2(__hmax2(__hadd2(v, three), zero), six);
    return __hmul2(v, c);
}

// ---------------------------------------------------------------------------
// Prep kernel: one block per layer; converts fp32 weights to the
// fragment-swizzled fp16 planes (identical values to the old in-kernel path).
// ---------------------------------------------------------------------------
__global__ void prep_weights(
    const float* __restrict__ w11, const float* __restrict__ w21,
    const float* __restrict__ w12, const float* __restrict__ w22)
{
    const int l = blockIdx.x;
    const int tid = threadIdx.x;

    const float* g11 = w11 + l * 8192;
    const float* g21 = w21 + l * 8192;
    for (int i = tid; i < 8192; i += 256) {
        int d = i >> 5, k = i & 31;
        int kt = k >> 4, rrr = k & 15;
        int tgp, pos;
        if (rrr < 8) { tgp = rrr >> 1; pos = rrr & 1; }
        else         { tgp = (rrr - 8) >> 1; pos = 2 + (rrr & 1); }
        int idx = d * 32 + tgp * 8 + kt * 4 + pos;
        gW1[l][0][idx] = __float2half_rn(g11[i]);
        gW1[l][1][idx] = __float2half_rn(g21[i]);
    }
    const float* g12 = w12 + l * 8192;
    const float* g22 = w22 + l * 8192;
    for (int i = tid; i < 8192; i += 256) {
        int n = i >> 8, k = i & 255;
        int ktile = k >> 4, rrr = k & 15;
        int tgp, pos;
        if (rrr < 8) { tgp = rrr >> 1; pos = rrr & 1; }
        else         { tgp = (rrr - 8) >> 1; pos = 2 + (rrr & 1); }
        int idx = n * 288 + ((ktile >> 1) * 4 + tgp) * 8 + (ktile & 1) * 4 + pos;
        gW2[l][0][idx] = __float2half_rn(g12[i] * (1.0f / 6.0f));
        gW2[l][1][idx] = __float2half_rn(g22[i] * (1.0f / 6.0f));
    }
}

// One mixing branch (identical math to R12).
template <bool TOKEN>
__device__ __forceinline__ void mix_branch_mma(
    float* h, float* st,
    const __half* w1, const __half* w2,
    const float* b1, const float* b2,
    const float* g, const float* bb, int lane)
{
    const int gid = lane >> 2;
    const int tg  = lane & 3;

    float s = 0.f, q = 0.f;
    #pragma unroll
    for (int j = 0; j < 32; j += 2) {
        float2 v = *reinterpret_cast<const float2*>(h + lane * 34 + j);
        s += v.x + v.y; q += v.x * v.x + v.y * v.y;
    }
    float m = s * 0.03125f;
    float r = rsqrtf(fmaxf(q * 0.03125f - m * m, 0.f) + MIX_EPS);
    st[lane] = m; st[32 + lane] = r;
    __syncwarp();

    unsigned a1[2][2][4];
    #pragma unroll
    for (int mt = 0; mt < 2; mt++)
    #pragma unroll
    for (int kt = 0; kt < 2; kt++) {
        #pragma unroll
        for (int rr = 0; rr < 2; rr++) {
            int am = mt * 16 + gid + rr * 8;
            #pragma unroll
            for (int cc = 0; cc < 2; cc++) {
                int ak = kt * 16 + tg * 2 + cc * 8;
                float v0, v1;
                if (TOKEN) {
                    float x0 = h[ak * 34 + am];
                    float x1 = h[(ak + 1) * 34 + am];
                    float gm = g[am], bm = bb[am];
                    v0 = (x0 - st[ak]) * st[32 + ak] * gm + bm;
                    v1 = (x1 - st[ak + 1]) * st[32 + ak + 1] * gm + bm;
                } else {
                    float2 x = *reinterpret_cast<const float2*>(h + am * 34 + ak);
                    float mm = st[am], ri = st[32 + am];
                    v0 = (x.x - mm) * ri * g[ak] + bb[ak];
                    v1 = (x.y - mm) * ri * g[ak + 1] + bb[ak + 1];
                }
                __half2 hv = __floats2half2_rn(v0, v1);
                a1[mt][kt][rr + cc * 2] = *reinterpret_cast<unsigned*>(&hv);
            }
        }
    }

    float outacc[2][4][4];
    #pragma unroll
    for (int ntO = 0; ntO < 4; ntO++) {
        int c = ntO * 8 + tg * 2;
        float bv0 = b2[c], bv1 = b2[c + 1];
        #pragma unroll
        for (int mt = 0; mt < 2; mt++) {
            outacc[mt][ntO][0] = bv0; outacc[mt][ntO][1] = bv1;
            outacc[mt][ntO][2] = bv0; outacc[mt][ntO][3] = bv1;
        }
    }

    for (int nc = 0; nc < 4; nc++) {
        float dAcc[2][8][4];
        #pragma unroll
        for (int nt = 0; nt < 8; nt++) {
            float2 bv = *reinterpret_cast<const float2*>(
                b1 + nc * 64 + nt * 8 + tg * 2);
            #pragma unroll
            for (int mt = 0; mt < 2; mt++) {
                dAcc[mt][nt][0] = bv.x; dAcc[mt][nt][1] = bv.y;
                dAcc[mt][nt][2] = bv.x; dAcc[mt][nt][3] = bv.y;
            }
        }

        #pragma unroll
        for (int nt = 0; nt < 8; nt++) {
            int n = nc * 64 + nt * 8 + gid;
            uint4 f = *reinterpret_cast<const uint4*>(w1 + n * 32 + tg * 8);
            mma16816(dAcc[0][nt], a1[0][0], f.x, f.y);
            mma16816(dAcc[1][nt], a1[1][0], f.x, f.y);
            mma16816(dAcc[0][nt], a1[0][1], f.z, f.w);
            mma16816(dAcc[1][nt], a1[1][1], f.z, f.w);
        }

        #pragma unroll
        for (int j = 0; j < 2; j++) {
            uint4 fw[4];
            #pragma unroll
            for (int ntO = 0; ntO < 4; ntO++) {
                int n = ntO * 8 + gid;
                fw[ntO] = *reinterpret_cast<const uint4*>(
                    w2 + n * 288 + ((nc * 2 + j) * 4 + tg) * 8);
            }
            #pragma unroll
            for (int p = 0; p < 2; p++) {
                int kt2 = 2 * j + p;
                unsigned a2[2][4];
                #pragma unroll
                for (int part = 0; part < 2; part++) {
                    int nt = 2 * kt2 + part;
                    #pragma unroll
                    for (int mt = 0; mt < 2; mt++) {
                        __half2 ha = __floats2half2_rn(dAcc[mt][nt][0],
                                                       dAcc[mt][nt][1]);
                        __half2 hb = __floats2half2_rn(dAcc[mt][nt][2],
                                                       dAcc[mt][nt][3]);
                        __half2 ra = hswish2(ha);
                        __half2 rb = hswish2(hb);
                        a2[mt][part * 2 + 0] = *reinterpret_cast<unsigned*>(&ra);
                        a2[mt][part * 2 + 1] = *reinterpret_cast<unsigned*>(&rb);
                    }
                }
                #pragma unroll
                for (int ntO = 0; ntO < 4; ntO++) {
                    unsigned b0 = p ? fw[ntO].z : fw[ntO].x;
                    unsigned b1r = p ? fw[ntO].w : fw[ntO].y;
                    mma16816(outacc[0][ntO], a2[0], b0, b1r);
                    mma16816(outacc[1][ntO], a2[1], b0, b1r);
                }
            }
        }
    }

    if (TOKEN) {
        #pragma unroll
        for (int mt = 0; mt < 2; mt++)
        #pragma unroll
        for (int ntO = 0; ntO < 4; ntO++) {
            int mm = mt * 16 + gid;
            int nn = ntO * 8 + tg * 2;
            h[nn * 34 + mm]           += outacc[mt][ntO][0];
            h[(nn + 1) * 34 + mm]     += outacc[mt][ntO][1];
            h[nn * 34 + mm + 8]       += outacc[mt][ntO][2];
            h[(nn + 1) * 34 + mm + 8] += outacc[mt][ntO][3];
        }
    } else {
        #pragma unroll
        for (int mt = 0; mt < 2; mt++)
        #pragma unroll
        for (int ntO = 0; ntO < 4; ntO++) {
            int rr0 = mt * 16 + gid;
            int c = ntO * 8 + tg * 2;
            float2* p0 = reinterpret_cast<float2*>(h + rr0 * 34 + c);
            float2 v0 = *p0;
            v0.x += outacc[mt][ntO][0]; v0.y += outacc[mt][ntO][1];
            *p0 = v0;
            float2* p1 = reinterpret_cast<float2*>(h + (rr0 + 8) * 34 + c);
            float2 v1 = *p1;
            v1.x += outacc[mt][ntO][2]; v1.y += outacc[mt][ntO][3];
            *p1 = v1;
        }
    }
    __syncwarp();
}

extern __shared__ char smem_raw[];

__global__ __launch_bounds__(NTHREADS, 2)
void mixer_kernel(
    const float* __restrict__ x,
    const float* __restrict__ conv_w, const float* __restrict__ conv_b,
    const float* __restrict__ fc0_w,  const float* __restrict__ fc0_b,
    const float* __restrict__ ln1_g,  const float* __restrict__ ln1_b,
    const float* __restrict__ b11,    const float* __restrict__ b12,
    const float* __restrict__ ln2_g,  const float* __restrict__ ln2_b,
    const float* __restrict__ b21,    const float* __restrict__ b22,
    const float* __restrict__ fc1_w,  const float* __restrict__ fc1_b,
    const float* __restrict__ fcout_w,const float* __restrict__ fcout_b,
    float* __restrict__ out, int B)
{
    const int tid = threadIdx.x;
    const int lane = tid & 31;
    const int wid = tid >> 5;      // 0..7, one element per warp

    float* sH   = reinterpret_cast<float*>(smem_raw + OFF_H);
    float* sSt  = reinterpret_cast<float*>(smem_raw + OFF_ST);
    float* sB1t = reinterpret_cast<float*>(smem_raw + OFF_B1T);
    float* sB1c = reinterpret_cast<float*>(smem_raw + OFF_B1C);
    float* sB2t = reinterpret_cast<float*>(smem_raw + OFF_B2T);
    float* sB2c = reinterpret_cast<float*>(smem_raw + OFF_B2C);
    float* sL1g = reinterpret_cast<float*>(smem_raw + OFF_LN1G);
    float* sL1b = reinterpret_cast<float*>(smem_raw + OFF_LN1B);
    float* sL2g = reinterpret_cast<float*>(smem_raw + OFF_LN2G);
    float* sL2b = reinterpret_cast<float*>(smem_raw + OFF_LN2B);
    __half* w1t = reinterpret_cast<__half*>(smem_raw + OFF_W1T);
    __half* w1c = reinterpret_cast<__half*>(smem_raw + OFF_W1C);
    __half* w2t = reinterpret_cast<__half*>(smem_raw + OFF_W2T);
    __half* w2c = reinterpret_cast<__half*>(smem_raw + OFF_W2C);
    float* sFw = reinterpret_cast<float*>(smem_raw + OFF_WT);
    float* sFo = reinterpret_cast<float*>(smem_raw + OFF_W1C);

    const int eb = blockIdx.x * NWARPS + wid;
    const bool act = (eb < B);
    float* h  = sH + wid * (32 * 34);
    float* st = sSt + wid * 64;

    // ---- stage fc0 weights, preprocess (conv1x1 + fc0) ----
    for (int i = tid; i < 1024; i += NTHREADS) sFw[i] = fc0_w[i];
    if (tid < 32) sB1t[tid] = fc0_b[tid];
    __syncthreads();

    if (act) {
        const float cw0 = conv_w[0], cw1 = conv_w[1], cw2 = conv_w[2];
        const float cb  = conv_b[0];
        const float* xb = x + (size_t)eb * 3072 + lane * 32;
        float2 gp[16];
        #pragma unroll
        for (int qq = 0; qq < 8; qq++) {
            float4 v0 = *reinterpret_cast<const float4*>(xb + qq * 4);
            float4 v1 = *reinterpret_cast<const float4*>(xb + 1024 + qq * 4);
            float4 v2 = *reinterpret_cast<const float4*>(xb + 2048 + qq * 4);
            gp[2 * qq]     = make_float2(cw0 * v0.x + cw1 * v1.x + cw2 * v2.x + cb,
                                         cw0 * v0.y + cw1 * v1.y + cw2 * v2.y + cb);
            gp[2 * qq + 1] = make_float2(cw0 * v0.z + cw1 * v1.z + cw2 * v2.z + cb,
                                         cw0 * v0.w + cw1 * v1.w + cw2 * v2.w + cb);
        }
        for (int j = 0; j < 32; j++) {
            const float4* wq = reinterpret_cast<const float4*>(sFw + j * 32);
            float2 acc = make_float2(0.f, 0.f), accb = make_float2(0.f, 0.f);
            #pragma unroll
            for (int qq = 0; qq < 8; qq++) {
                float4 w = wq[qq];
                acc  = ffma2(gp[2 * qq],     make_float2(w.x, w.y), acc);
                accb = ffma2(gp[2 * qq + 1], make_float2(w.z, w.w), accb);
            }
            float2 sv = fadd2(acc, accb);
            h[lane * 34 + j] = sv.x + sv.y + sB1t[j];
        }
    }
    __syncthreads();

    // ---- 8 layers x 2 repeats ----
    for (int l = 0; l < 8; l++) {
        // stage pre-converted weight planes: pure uint4 copies
        {
            const uint4* s1t = reinterpret_cast<const uint4*>(gW1[l][0]);
            const uint4* s1c = reinterpret_cast<const uint4*>(gW1[l][1]);
            uint4* d1t = reinterpret_cast<uint4*>(w1t);
            uint4* d1c = reinterpret_cast<uint4*>(w1c);
            #pragma unroll
            for (int i = tid; i < 1024; i += NTHREADS) {
                d1t[i] = s1t[i];
                d1c[i] = s1c[i];
            }
            const uint4* s2t = reinterpret_cast<const uint4*>(gW2[l][0]);
            const uint4* s2c = reinterpret_cast<const uint4*>(gW2[l][1]);
            uint4* d2t = reinterpret_cast<uint4*>(w2t);
            uint4* d2c = reinterpret_cast<uint4*>(w2c);
            #pragma unroll
            for (int i = tid; i < 1152; i += NTHREADS) {
                d2t[i] = s2t[i];
                d2c[i] = s2c[i];
            }
            if (tid < 256) { sB1t[tid] = b11[l * 256 + tid]; sB1c[tid] = b21[l * 256 + tid]; }
            if (tid < 32) {
                sB2t[tid] = b12[l * 32 + tid];
                sB2c[tid] = b22[l * 32 + tid];
                sL1g[tid] = ln1_g[l * 32 + tid];
                sL1b[tid] = ln1_b[l * 32 + tid];
                sL2g[tid] = ln2_g[l * 32 + tid];
                sL2b[tid] = ln2_b[l * 32 + tid];
            }
        }
        __syncthreads();

        if (act) {
            for (int rep = 0; rep < 2; rep++) {
                mix_branch_mma<true >(h, st, w1t, w2t, sB1t, sB2t, sL1g, sL1b, lane);
                mix_branch_mma<false>(h, st, w1c, w2c, sB1c, sB2c, sL2g, sL2b, lane);
            }
        }
        __syncthreads();
    }

    // ---- head: fc1 + hardswish + avgpool(32) + fcout ----
    {
        const float4* s1 = reinterpret_cast<const float4*>(fc1_w);
        float4* d1 = reinterpret_cast<float4*>(sFw);
        for (int i = tid; i < 1024; i += NTHREADS) d1[i] = s1[i];
        for (int i = tid; i < 1280; i += NTHREADS) sFo[i] = fcout_w[i];
        if (tid < 128) sB1t[tid] = fc1_b[tid];
        if (tid < 10)  sB2t[tid] = fcout_b[tid];
    }
    __syncthreads();

    if (act) {
        float2 ap[16];
        #pragma unroll
        for (int t = 0; t < 16; t++)
            ap[t] = *reinterpret_cast<const float2*>(h + lane * 34 + 2 * t);
        float pool[4] = {0.f, 0.f, 0.f, 0.f};
        for (int d = 0; d < 128; d++) {
            const float4* wq = reinterpret_cast<const float4*>(sFw + d * 32);
            float2 acc = make_float2(0.f, 0.f), accb = make_float2(0.f, 0.f);
            #pragma unroll
            for (int qq = 0; qq < 8; qq++) {
                float4 w = wq[qq];
                acc  = ffma2(ap[2 * qq],     make_float2(w.x, w.y), acc);
                accb = ffma2(ap[2 * qq + 1], make_float2(w.z, w.w), accb);
            }
            float2 sv = fadd2(acc, accb);
            float v = sv.x + sv.y + sB1t[d];
            float y = v * fminf(fmaxf(v + 3.0f, 0.0f), 6.0f) * (1.0f / 6.0f);
            pool[d >> 5] += y;
        }
        #pragma unroll
        for (int p = 0; p < 4; p++) pool[p] *= (1.0f / 32.0f);
        #pragma unroll
        for (int o = 0; o < 10; o++) {
            float4 wv = *reinterpret_cast<const float4*>(sFo + o * 128 + lane * 4);
            float v = pool[0] * wv.x + pool[1] * wv.y + pool[2] * wv.z + pool[3] * wv.w;
            #pragma unroll
            for (int sft = 16; sft > 0; sft >>= 1)
                v += __shfl_xor_sync(0xffffffffu, v, sft);
            if (lane == 0) out[(size_t)eb * 10 + o] = v + sB2t[o];
        }
    }
}

extern "C" void kernel_launch(void* const* d_in, const int* in_sizes, int n_in,
                              void* d_out, int out_size) {
    const float* x       = (const float*)d_in[0];
    const float* conv_w  = (const float*)d_in[1];
    const float* conv_b  = (const float*)d_in[2];
    const float* fc0_w   = (const float*)d_in[3];
    const float* fc0_b   = (const float*)d_in[4];
    const float* ln1_g   = (const float*)d_in[5];
    const float* ln1_b   = (const float*)d_in[6];
    const float* w11     = (const float*)d_in[7];
    const float* b11     = (const float*)d_in[8];
    const float* w12     = (const float*)d_in[9];
    const float* b12     = (const float*)d_in[10];
    const float* ln2_g   = (const float*)d_in[11];
    const float* ln2_b   = (const float*)d_in[12];
    const float* w21     = (const float*)d_in[13];
    const float* b21     = (const float*)d_in[14];
    const float* w22     = (const float*)d_in[15];
    const float* b22     = (const float*)d_in[16];
    const float* fc1_w   = (const float*)d_in[17];
    const float* fc1_b   = (const float*)d_in[18];
    const float* fcout_w = (const float*)d_in[19];
    const float* fcout_b = (const float*)d_in[20];
    float* out = (float*)d_out;

    const int B = in_sizes[0] / 3072;
    const int blocks = (B + NWARPS - 1) / NWARPS;

    prep_weights<<<8, 256>>>(w11, w21, w12, w22);

    cudaFuncSetAttribute(mixer_kernel,
                         cudaFuncAttributeMaxDynamicSharedMemorySize,
                         SMEM_BYTES);
    mixer_kernel<<<blocks, NTHREADS, SMEM_BYTES>>>(
        x, conv_w, conv_b, fc0_w, fc0_b, ln1_g, ln1_b,
        b11, b12, ln2_g, ln2_b, b21, b22,
        fc1_w, fc1_b, fcout_w, fcout_b, out, B);
}

// round 15
// speedup vs baseline: 1.2826x; 1.0005x over previous
#include <cuda_runtime.h>
#include <cuda_fp16.h>

// ---------------------------------------------------------------------------
// MLP-Mixer on tensor cores, round 13: R12 (two 8-warp CTAs/SM, single-pass
// fp16 C = Ah @ Bh, LDS.128 fragment weights, half2 epilogue) + weight
// conversion HOISTED into a one-shot prep kernel writing fragment-swizzled
// fp16 planes to __device__ globals. Main-kernel staging is now a pure
// LDG.128->STS.128 copy (17 uint4/thread/layer) instead of 2x8192 scalar
// convert+scatter iterations (~1/3 of the old instruction stream, and the
// dominant L1-wavefront source).
// ---------------------------------------------------------------------------

#define MIX_EPS 1e-5f
#define NTHREADS 256
#define NWARPS 8

// ---- converted-weight globals (fragment-swizzled fp16 planes) ----
// w1 plane: 256 rows * 32 halves; w2 plane: 32 rows * 288 halves.
__device__ __half gW1[8][2][256 * 32];
__device__ __half gW2[8][2][32 * 288];

// ---- SMEM byte offsets ----
#define OFF_H     0         // 8 * 32*34 * 4 = 34816
#define OFF_ST    34816     // 8 * 64 * 4 = 2048
#define OFF_B1T   36864     // 256 f
#define OFF_B1C   37888
#define OFF_B2T   38912     // 32 f
#define OFF_B2C   39040
#define OFF_LN1G  39168
#define OFF_LN1B  39296
#define OFF_LN2G  39424
#define OFF_LN2B  39552
#define OFF_WT    39680     // weight region (also fp32 staging for pre/head)
#define OFF_W1T   39680     // 16384
#define OFF_W1C   56064     // 16384
#define OFF_W2T   72448     // 18432
#define OFF_W2C   90880     // 18432
#define SMEM_BYTES 109312   // 2 CTAs/SM

__device__ __forceinline__ float2 ffma2(float2 a, float2 b, float2 c) {
    unsigned long long au = *reinterpret_cast<unsigned long long*>(&a);
    unsigned long long bu = *reinterpret_cast<unsigned long long*>(&b);
    unsigned long long cu = *reinterpret_cast<unsigned long long*>(&c);
    unsigned long long du;
    asm("fma.rn.f32x2 %0, %1, %2, %3;" : "=l"(du) : "l"(au), "l"(bu), "l"(cu));
    return *reinterpret_cast<float2*>(&du);
}
__device__ __forceinline__ float2 fadd2(float2 a, float2 b) {
    unsigned long long au = *reinterpret_cast<unsigned long long*>(&a);
    unsigned long long bu = *reinterpret_cast<unsigned long long*>(&b);
    unsigned long long du;
    asm("add.rn.f32x2 %0, %1, %2;" : "=l"(du) : "l"(au), "l"(bu));
    return *reinterpret_cast<float2*>(&du);
}

__device__ __forceinline__ void mma16816(float d[4], const unsigned a[4],
                                         unsigned b0, unsigned b1) {
    asm volatile(
        "mma.sync.aligned.m16n8k16.row.col.f32.f16.f16.f32 "
        "{%0,%1,%2,%3}, {%4,%5,%6,%7}, {%8,%9}, {%0,%1,%2,%3};\n"
        : "+f"(d[0]), "+f"(d[1]), "+f"(d[2]), "+f"(d[3])
        : "r"(a[0]), "r"(a[1]), "r"(a[2]), "r"(a[3]), "r"(b0), "r"(b1));
}

__device__ __forceinline__ __half2 hswish2(__half2 v) {
    const __half2 three = __floats2half2_rn(3.f, 3.f);
    const __half2 six   = __floats2half2_rn(6.f, 6.f);
    const __half2 zero  = __floats2half2_rn(0.f, 0.f);
    __half2 c = __hmin2(__hmax2(__hadd2(v, three), zero), six);
    return __hmul2(v, c);
}

// ---------------------------------------------------------------------------
// Prep kernel: one block per layer; converts fp32 weights to the
// fragment-swizzled fp16 planes (identical values to the old in-kernel path).
// ---------------------------------------------------------------------------
__global__ void prep_weights(
    const float* __restrict__ w11, const float* __restrict__ w21,
    const float* __restrict__ w12, const float* __restrict__ w22)
{
    const int l = blockIdx.x;
    const int tid = threadIdx.x;

    const float* g11 = w11 + l * 8192;
    const float* g21 = w21 + l * 8192;
    for (int i = tid; i < 8192; i += 256) {
        int d = i >> 5, k = i & 31;
        int kt = k >> 4, rrr = k & 15;
        int tgp, pos;
        if (rrr < 8) { tgp = rrr >> 1; pos = rrr & 1; }
        else         { tgp = (rrr - 8) >> 1; pos = 2 + (rrr & 1); }
        int idx = d * 32 + tgp * 8 + kt * 4 + pos;
        gW1[l][0][idx] = __float2half_rn(g11[i]);
        gW1[l][1][idx] = __float2half_rn(g21[i]);
    }
    const float* g12 = w12 + l * 8192;
    const float* g22 = w22 + l * 8192;
    for (int i = tid; i < 8192; i += 256) {
        int n = i >> 8, k = i & 255;
        int ktile = k >> 4, rrr = k & 15;
        int tgp, pos;
        if (rrr < 8) { tgp = rrr >> 1; pos = rrr & 1; }
        else         { tgp = (rrr - 8) >> 1; pos = 2 + (rrr & 1); }
        int idx = n * 288 + ((ktile >> 1) * 4 + tgp) * 8 + (ktile & 1) * 4 + pos;
        gW2[l][0][idx] = __float2half_rn(g12[i] * (1.0f / 6.0f));
        gW2[l][1][idx] = __float2half_rn(g22[i] * (1.0f / 6.0f));
    }
}

// One mixing branch (identical math to R12).
template <bool TOKEN>
__device__ __forceinline__ void mix_branch_mma(
    float* h, float* st,
    const __half* w1, const __half* w2,
    const float* b1, const float* b2,
    const float* g, const float* bb, int lane)
{
    const int gid = lane >> 2;
    const int tg  = lane & 3;

    float s = 0.f, q = 0.f;
    #pragma unroll
    for (int j = 0; j < 32; j += 2) {
        float2 v = *reinterpret_cast<const float2*>(h + lane * 34 + j);
        s += v.x + v.y; q += v.x * v.x + v.y * v.y;
    }
    float m = s * 0.03125f;
    float r = rsqrtf(fmaxf(q * 0.03125f - m * m, 0.f) + MIX_EPS);
    st[lane] = m; st[32 + lane] = r;
    __syncwarp();

    unsigned a1[2][2][4];
    #pragma unroll
    for (int mt = 0; mt < 2; mt++)
    #pragma unroll
    for (int kt = 0; kt < 2; kt++) {
        #pragma unroll
        for (int rr = 0; rr < 2; rr++) {
            int am = mt * 16 + gid + rr * 8;
            #pragma unroll
            for (int cc = 0; cc < 2; cc++) {
                int ak = kt * 16 + tg * 2 + cc * 8;
                float v0, v1;
                if (TOKEN) {
                    float x0 = h[ak * 34 + am];
                    float x1 = h[(ak + 1) * 34 + am];
                    float gm = g[am], bm = bb[am];
                    v0 = (x0 - st[ak]) * st[32 + ak] * gm + bm;
                    v1 = (x1 - st[ak + 1]) * st[32 + ak + 1] * gm + bm;
                } else {
                    float2 x = *reinterpret_cast<const float2*>(h + am * 34 + ak);
                    float mm = st[am], ri = st[32 + am];
                    v0 = (x.x - mm) * ri * g[ak] + bb[ak];
                    v1 = (x.y - mm) * ri * g[ak + 1] + bb[ak + 1];
                }
                __half2 hv = __floats2half2_rn(v0, v1);
                a1[mt][kt][rr + cc * 2] = *reinterpret_cast<unsigned*>(&hv);
            }
        }
    }

    float outacc[2][4][4];
    #pragma unroll
    for (int ntO = 0; ntO < 4; ntO++) {
        int c = ntO * 8 + tg * 2;
        float bv0 = b2[c], bv1 = b2[c + 1];
        #pragma unroll
        for (int mt = 0; mt < 2; mt++) {
            outacc[mt][ntO][0] = bv0; outacc[mt][ntO][1] = bv1;
            outacc[mt][ntO][2] = bv0; outacc[mt][ntO][3] = bv1;
        }
    }

    for (int nc = 0; nc < 4; nc++) {
        float dAcc[2][8][4];
        #pragma unroll
        for (int nt = 0; nt < 8; nt++) {
            float2 bv = *reinterpret_cast<const float2*>(
                b1 + nc * 64 + nt * 8 + tg * 2);
            #pragma unroll
            for (int mt = 0; mt < 2; mt++) {
                dAcc[mt][nt][0] = bv.x; dAcc[mt][nt][1] = bv.y;
                dAcc[mt][nt][2] = bv.x; dAcc[mt][nt][3] = bv.y;
            }
        }

        #pragma unroll
        for (int nt = 0; nt < 8; nt++) {
            int n = nc * 64 + nt * 8 + gid;
            uint4 f = *reinterpret_cast<const uint4*>(w1 + n * 32 + tg * 8);
            mma16816(dAcc[0][nt], a1[0][0], f.x, f.y);
            mma16816(dAcc[1][nt], a1[1][0], f.x, f.y);
            mma16816(dAcc[0][nt], a1[0][1], f.z, f.w);
            mma16816(dAcc[1][nt], a1[1][1], f.z, f.w);
        }

        #pragma unroll
        for (int j = 0; j < 2; j++) {
            uint4 fw[4];
            #pragma unroll
            for (int ntO = 0; ntO < 4; ntO++) {
                int n = ntO * 8 + gid;
                fw[ntO] = *reinterpret_cast<const uint4*>(
                    w2 + n * 288 + ((nc * 2 + j) * 4 + tg) * 8);
            }
            #pragma unroll
            for (int p = 0; p < 2; p++) {
                int kt2 = 2 * j + p;
                unsigned a2[2][4];
                #pragma unroll
                for (int part = 0; part < 2; part++) {
                    int nt = 2 * kt2 + part;
                    #pragma unroll
                    for (int mt = 0; mt < 2; mt++) {
                        __half2 ha = __floats2half2_rn(dAcc[mt][nt][0],
                                                       dAcc[mt][nt][1]);
                        __half2 hb = __floats2half2_rn(dAcc[mt][nt][2],
                                                       dAcc[mt][nt][3]);
                        __half2 ra = hswish2(ha);
                        __half2 rb = hswish2(hb);
                        a2[mt][part * 2 + 0] = *reinterpret_cast<unsigned*>(&ra);
                        a2[mt][part * 2 + 1] = *reinterpret_cast<unsigned*>(&rb);
                    }
                }
                #pragma unroll
                for (int ntO = 0; ntO < 4; ntO++) {
                    unsigned b0 = p ? fw[ntO].z : fw[ntO].x;
                    unsigned b1r = p ? fw[ntO].w : fw[ntO].y;
                    mma16816(outacc[0][ntO], a2[0], b0, b1r);
                    mma16816(outacc[1][ntO], a2[1], b0, b1r);
                }
            }
        }
    }

    if (TOKEN) {
        #pragma unroll
        for (int mt = 0; mt < 2; mt++)
        #pragma unroll
        for (int ntO = 0; ntO < 4; ntO++) {
            int mm = mt * 16 + gid;
            int nn = ntO * 8 + tg * 2;
            h[nn * 34 + mm]           += outacc[mt][ntO][0];
            h[(nn + 1) * 34 + mm]     += outacc[mt][ntO][1];
            h[nn * 34 + mm + 8]       += outacc[mt][ntO][2];
            h[(nn + 1) * 34 + mm + 8] += outacc[mt][ntO][3];
        }
    } else {
        #pragma unroll
        for (int mt = 0; mt < 2; mt++)
        #pragma unroll
        for (int ntO = 0; ntO < 4; ntO++) {
            int rr0 = mt * 16 + gid;
            int c = ntO * 8 + tg * 2;
            float2* p0 = reinterpret_cast<float2*>(h + rr0 * 34 + c);
            float2 v0 = *p0;
            v0.x += outacc[mt][ntO][0]; v0.y += outacc[mt][ntO][1];
            *p0 = v0;
            float2* p1 = reinterpret_cast<float2*>(h + (rr0 + 8) * 34 + c);
            float2 v1 = *p1;
            v1.x += outacc[mt][ntO][2]; v1.y += outacc[mt][ntO][3];
            *p1 = v1;
        }
    }
    __syncwarp();
}

extern __shared__ char smem_raw[];

__global__ __launch_bounds__(NTHREADS, 2)
void mixer_kernel(
    const float* __restrict__ x,
    const float* __restrict__ conv_w, const float* __restrict__ conv_b,
    const float* __restrict__ fc0_w,  const float* __restrict__ fc0_b,
    const float* __restrict__ ln1_g,  const float* __restrict__ ln1_b,
    const float* __restrict__ b11,    const float* __restrict__ b12,
    const float* __restrict__ ln2_g,  const float* __restrict__ ln2_b,
    const float* __restrict__ b21,    const float* __restrict__ b22,
    const float* __restrict__ fc1_w,  const float* __restrict__ fc1_b,
    const float* __restrict__ fcout_w,const float* __restrict__ fcout_b,
    float* __restrict__ out, int B)
{
    const int tid = threadIdx.x;
    const int lane = tid & 31;
    const int wid = tid >> 5;      // 0..7, one element per warp

    float* sH   = reinterpret_cast<float*>(smem_raw + OFF_H);
    float* sSt  = reinterpret_cast<float*>(smem_raw + OFF_ST);
    float* sB1t = reinterpret_cast<float*>(smem_raw + OFF_B1T);
    float* sB1c = reinterpret_cast<float*>(smem_raw + OFF_B1C);
    float* sB2t = reinterpret_cast<float*>(smem_raw + OFF_B2T);
    float* sB2c = reinterpret_cast<float*>(smem_raw + OFF_B2C);
    float* sL1g = reinterpret_cast<float*>(smem_raw + OFF_LN1G);
    float* sL1b = reinterpret_cast<float*>(smem_raw + OFF_LN1B);
    float* sL2g = reinterpret_cast<float*>(smem_raw + OFF_LN2G);
    float* sL2b = reinterpret_cast<float*>(smem_raw + OFF_LN2B);
    __half* w1t = reinterpret_cast<__half*>(smem_raw + OFF_W1T);
    __half* w1c = reinterpret_cast<__half*>(smem_raw + OFF_W1C);
    __half* w2t = reinterpret_cast<__half*>(smem_raw + OFF_W2T);
    __half* w2c = reinterpret_cast<__half*>(smem_raw + OFF_W2C);
    float* sFw = reinterpret_cast<float*>(smem_raw + OFF_WT);
    float* sFo = reinterpret_cast<float*>(smem_raw + OFF_W1C);

    const int eb = blockIdx.x * NWARPS + wid;
    const bool act = (eb < B);
    float* h  = sH + wid * (32 * 34);
    float* st = sSt + wid * 64;

    // ---- stage fc0 weights, preprocess (conv1x1 + fc0) ----
    for (int i = tid; i < 1024; i += NTHREADS) sFw[i] = fc0_w[i];
    if (tid < 32) sB1t[tid] = fc0_b[tid];
    __syncthreads();

    if (act) {
        const float cw0 = conv_w[0], cw1 = conv_w[1], cw2 = conv_w[2];
        const float cb  = conv_b[0];
        const float* xb = x + (size_t)eb * 3072 + lane * 32;
        float2 gp[16];
        #pragma unroll
        for (int qq = 0; qq < 8; qq++) {
            float4 v0 = *reinterpret_cast<const float4*>(xb + qq * 4);
            float4 v1 = *reinterpret_cast<const float4*>(xb + 1024 + qq * 4);
            float4 v2 = *reinterpret_cast<const float4*>(xb + 2048 + qq * 4);
            gp[2 * qq]     = make_float2(cw0 * v0.x + cw1 * v1.x + cw2 * v2.x + cb,
                                         cw0 * v0.y + cw1 * v1.y + cw2 * v2.y + cb);
            gp[2 * qq + 1] = make_float2(cw0 * v0.z + cw1 * v1.z + cw2 * v2.z + cb,
                                         cw0 * v0.w + cw1 * v1.w + cw2 * v2.w + cb);
        }
        for (int j = 0; j < 32; j++) {
            const float4* wq = reinterpret_cast<const float4*>(sFw + j * 32);
            float2 acc = make_float2(0.f, 0.f), accb = make_float2(0.f, 0.f);
            #pragma unroll
            for (int qq = 0; qq < 8; qq++) {
                float4 w = wq[qq];
                acc  = ffma2(gp[2 * qq],     make_float2(w.x, w.y), acc);
                accb = ffma2(gp[2 * qq + 1], make_float2(w.z, w.w), accb);
            }
            float2 sv = fadd2(acc, accb);
            h[lane * 34 + j] = sv.x + sv.y + sB1t[j];
        }
    }
    __syncthreads();

    // ---- 8 layers x 2 repeats ----
    for (int l = 0; l < 8; l++) {
        // stage pre-converted weight planes: pure uint4 copies
        {
            const uint4* s1t = reinterpret_cast<const uint4*>(gW1[l][0]);
            const uint4* s1c = reinterpret_cast<const uint4*>(gW1[l][1]);
            uint4* d1t = reinterpret_cast<uint4*>(w1t);
            uint4* d1c = reinterpret_cast<uint4*>(w1c);
            #pragma unroll
            for (int i = tid; i < 1024; i += NTHREADS) {
                d1t[i] = s1t[i];
                d1c[i] = s1c[i];
            }
            const uint4* s2t = reinterpret_cast<const uint4*>(gW2[l][0]);
            const uint4* s2c = reinterpret_cast<const uint4*>(gW2[l][1]);
            uint4* d2t = reinterpret_cast<uint4*>(w2t);
            uint4* d2c = reinterpret_cast<uint4*>(w2c);
            #pragma unroll
            for (int i = tid; i < 1152; i += NTHREADS) {
                d2t[i] = s2t[i];
                d2c[i] = s2c[i];
            }
            if (tid < 256) { sB1t[tid] = b11[l * 256 + tid]; sB1c[tid] = b21[l * 256 + tid]; }
            if (tid < 32) {
                sB2t[tid] = b12[l * 32 + tid];
                sB2c[tid] = b22[l * 32 + tid];
                sL1g[tid] = ln1_g[l * 32 + tid];
                sL1b[tid] = ln1_b[l * 32 + tid];
                sL2g[tid] = ln2_g[l * 32 + tid];
                sL2b[tid] = ln2_b[l * 32 + tid];
            }
        }
        __syncthreads();

        if (act) {
            for (int rep = 0; rep < 2; rep++) {
                mix_branch_mma<true >(h, st, w1t, w2t, sB1t, sB2t, sL1g, sL1b, lane);
                mix_branch_mma<false>(h, st, w1c, w2c, sB1c, sB2c, sL2g, sL2b, lane);
            }
        }
        __syncthreads();
    }

    // ---- head: fc1 + hardswish + avgpool(32) + fcout ----
    {
        const float4* s1 = reinterpret_cast<const float4*>(fc1_w);
        float4* d1 = reinterpret_cast<float4*>(sFw);
        for (int i = tid; i < 1024; i += NTHREADS) d1[i] = s1[i];
        for (int i = tid; i < 1280; i += NTHREADS) sFo[i] = fcout_w[i];
        if (tid < 128) sB1t[tid] = fc1_b[tid];
        if (tid < 10)  sB2t[tid] = fcout_b[tid];
    }
    __syncthreads();

    if (act) {
        float2 ap[16];
        #pragma unroll
        for (int t = 0; t < 16; t++)
            ap[t] = *reinterpret_cast<const float2*>(h + lane * 34 + 2 * t);
        float pool[4] = {0.f, 0.f, 0.f, 0.f};
        for (int d = 0; d < 128; d++) {
            const float4* wq = reinterpret_cast<const float4*>(sFw + d * 32);
            float2 acc = make_float2(0.f, 0.f), accb = make_float2(0.f, 0.f);
            #pragma unroll
            for (int qq = 0; qq < 8; qq++) {
                float4 w = wq[qq];
                acc  = ffma2(ap[2 * qq],     make_float2(w.x, w.y), acc);
                accb = ffma2(ap[2 * qq + 1], make_float2(w.z, w.w), accb);
            }
            float2 sv = fadd2(acc, accb);
            float v = sv.x + sv.y + sB1t[d];
            float y = v * fminf(fmaxf(v + 3.0f, 0.0f), 6.0f) * (1.0f / 6.0f);
            pool[d >> 5] += y;
        }
        #pragma unroll
        for (int p = 0; p < 4; p++) pool[p] *= (1.0f / 32.0f);
        #pragma unroll
        for (int o = 0; o < 10; o++) {
            float4 wv = *reinterpret_cast<const float4*>(sFo + o * 128 + lane * 4);
            float v = pool[0] * wv.x + pool[1] * wv.y + pool[2] * wv.z + pool[3] * wv.w;
            #pragma unroll
            for (int sft = 16; sft > 0; sft >>= 1)
                v += __shfl_xor_sync(0xffffffffu, v, sft);
            if (lane == 0) out[(size_t)eb * 10 + o] = v + sB2t[o];
        }
    }
}

extern "C" void kernel_launch(void* const* d_in, const int* in_sizes, int n_in,
                              void* d_out, int out_size) {
    const float* x       = (const float*)d_in[0];
    const float* conv_w  = (const float*)d_in[1];
    const float* conv_b  = (const float*)d_in[2];
    const float* fc0_w   = (const float*)d_in[3];
    const float* fc0_b   = (const float*)d_in[4];
    const float* ln1_g   = (const float*)d_in[5];
    const float* ln1_b   = (const float*)d_in[6];
    const float* w11     = (const float*)d_in[7];
    const float* b11     = (const float*)d_in[8];
    const float* w12     = (const float*)d_in[9];
    const float* b12     = (const float*)d_in[10];
    const float* ln2_g   = (const float*)d_in[11];
    const float* ln2_b   = (const float*)d_in[12];
    const float* w21     = (const float*)d_in[13];
    const float* b21     = (const float*)d_in[14];
    const float* w22     = (const float*)d_in[15];
    const float* b22     = (const float*)d_in[16];
    const float* fc1_w   = (const float*)d_in[17];
    const float* fc1_b   = (const float*)d_in[18];
    const float* fcout_w = (const float*)d_in[19];
    const float* fcout_b = (const float*)d_in[20];
    float* out = (float*)d_out;

    const int B = in_sizes[0] / 3072;
    const int blocks = (B + NWARPS - 1) / NWARPS;

    prep_weights<<<8, 256>>>(w11, w21, w12, w22);

    cudaFuncSetAttribute(mixer_kernel,
                         cudaFuncAttributeMaxDynamicSharedMemorySize,
                         SMEM_BYTES);
    mixer_kernel<<<blocks, NTHREADS, SMEM_BYTES>>>(
        x, conv_w, conv_b, fc0_w, fc0_b, ln1_g, ln1_b,
        b11, b12, ln2_g, ln2_b, b21, b22,
        fc1_w, fc1_b, fcout_w, fcout_b, out, B);
}

// round 17
// speedup vs baseline: 1.3096x; 1.0210x over previous
#include <cuda_runtime.h>
#include <cuda_fp16.h>

// ---------------------------------------------------------------------------
// MLP-Mixer on tensor cores, round 16: R13 (two 8-warp CTAs/SM, single-pass
// fp16 C = Ah @ Bh, prep-kernel fragment-swizzled weights, half2 epilogue)
// with the DIM=256 nc-loop fully unrolled: all mainloop LDS addresses become
// base+immediate (address-IMAD stream eliminated) and ptxas can hoist
// gemm1(nc+1) weight loads under gemm2(nc) MMAs. No math change.
// ---------------------------------------------------------------------------

#define MIX_EPS 1e-5f
#define NTHREADS 256
#define NWARPS 8

// ---- converted-weight globals (fragment-swizzled fp16 planes) ----
__device__ __half gW1[8][2][256 * 32];
__device__ __half gW2[8][2][32 * 288];

// ---- SMEM byte offsets ----
#define OFF_H     0         // 8 * 32*34 * 4 = 34816
#define OFF_ST    34816     // 2048
#define OFF_B1T   36864
#define OFF_B1C   37888
#define OFF_B2T   38912
#define OFF_B2C   39040
#define OFF_LN1G  39168
#define OFF_LN1B  39296
#define OFF_LN2G  39424
#define OFF_LN2B  39552
#define OFF_WT    39680
#define OFF_W1T   39680     // 16384
#define OFF_W1C   56064     // 16384
#define OFF_W2T   72448     // 18432
#define OFF_W2C   90880     // 18432
#define SMEM_BYTES 109312   // 2 CTAs/SM

__device__ __forceinline__ float2 ffma2(float2 a, float2 b, float2 c) {
    unsigned long long au = *reinterpret_cast<unsigned long long*>(&a);
    unsigned long long bu = *reinterpret_cast<unsigned long long*>(&b);
    unsigned long long cu = *reinterpret_cast<unsigned long long*>(&c);
    unsigned long long du;
    asm("fma.rn.f32x2 %0, %1, %2, %3;" : "=l"(du) : "l"(au), "l"(bu), "l"(cu));
    return *reinterpret_cast<float2*>(&du);
}
__device__ __forceinline__ float2 fadd2(float2 a, float2 b) {
    unsigned long long au = *reinterpret_cast<unsigned long long*>(&a);
    unsigned long long bu = *reinterpret_cast<unsigned long long*>(&b);
    unsigned long long du;
    asm("add.rn.f32x2 %0, %1, %2;" : "=l"(du) : "l"(au), "l"(bu));
    return *reinterpret_cast<float2*>(&du);
}

__device__ __forceinline__ void mma16816(float d[4], const unsigned a[4],
                                         unsigned b0, unsigned b1) {
    asm volatile(
        "mma.sync.aligned.m16n8k16.row.col.f32.f16.f16.f32 "
        "{%0,%1,%2,%3}, {%4,%5,%6,%7}, {%8,%9}, {%0,%1,%2,%3};\n"
        : "+f"(d[0]), "+f"(d[1]), "+f"(d[2]), "+f"(d[3])
        : "r"(a[0]), "r"(a[1]), "r"(a[2]), "r"(a[3]), "r"(b0), "r"(b1));
}

__device__ __forceinline__ __half2 hswish2(__half2 v) {
    const __half2 three = __floats2half2_rn(3.f, 3.f);
    const __half2 six   = __floats2half2_rn(6.f, 6.f);
    const __half2 zero  = __floats2half2_rn(0.f, 0.f);
    __half2 c = __hmin2(__hmax2(__hadd2(v, three), zero), six);
    return __hmul2(v, c);
}

// ---------------------------------------------------------------------------
// Prep kernel (identical to R13).
// ---------------------------------------------------------------------------
__global__ void prep_weights(
    const float* __restrict__ w11, const float* __restrict__ w21,
    const float* __restrict__ w12, const float* __restrict__ w22)
{
    const int l = blockIdx.x;
    const int tid = threadIdx.x;

    const float* g11 = w11 + l * 8192;
    const float* g21 = w21 + l * 8192;
    for (int i = tid; i < 8192; i += 256) {
        int d = i >> 5, k = i & 31;
        int kt = k >> 4, rrr = k & 15;
        int tgp, pos;
        if (rrr < 8) { tgp = rrr >> 1; pos = rrr & 1; }
        else         { tgp = (rrr - 8) >> 1; pos = 2 + (rrr & 1); }
        int idx = d * 32 + tgp * 8 + kt * 4 + pos;
        gW1[l][0][idx] = __float2half_rn(g11[i]);
        gW1[l][1][idx] = __float2half_rn(g21[i]);
    }
    const float* g12 = w12 + l * 8192;
    const float* g22 = w22 + l * 8192;
    for (int i = tid; i < 8192; i += 256) {
        int n = i >> 8, k = i & 255;
        int ktile = k >> 4, rrr = k & 15;
        int tgp, pos;
        if (rrr < 8) { tgp = rrr >> 1; pos = rrr & 1; }
        else         { tgp = (rrr - 8) >> 1; pos = 2 + (rrr & 1); }
        int idx = n * 288 + ((ktile >> 1) * 4 + tgp) * 8 + (ktile & 1) * 4 + pos;
        gW2[l][0][idx] = __float2half_rn(g12[i] * (1.0f / 6.0f));
        gW2[l][1][idx] = __float2half_rn(g22[i] * (1.0f / 6.0f));
    }
}

// One mixing branch (identical math to R13; nc loop fully unrolled).
template <bool TOKEN>
__device__ __forceinline__ void mix_branch_mma(
    float* h, float* st,
    const __half* w1, const __half* w2,
    const float* b1, const float* b2,
    const float* g, const float* bb, int lane)
{
    const int gid = lane >> 2;
    const int tg  = lane & 3;

    float s = 0.f, q = 0.f;
    #pragma unroll
    for (int j = 0; j < 32; j += 2) {
        float2 v = *reinterpret_cast<const float2*>(h + lane * 34 + j);
        s += v.x + v.y; q += v.x * v.x + v.y * v.y;
    }
    float m = s * 0.03125f;
    float r = rsqrtf(fmaxf(q * 0.03125f - m * m, 0.f) + MIX_EPS);
    st[lane] = m; st[32 + lane] = r;
    __syncwarp();

    unsigned a1[2][2][4];
    #pragma unroll
    for (int mt = 0; mt < 2; mt++)
    #pragma unroll
    for (int kt = 0; kt < 2; kt++) {
        #pragma unroll
        for (int rr = 0; rr < 2; rr++) {
            int am = mt * 16 + gid + rr * 8;
            #pragma unroll
            for (int cc = 0; cc < 2; cc++) {
                int ak = kt * 16 + tg * 2 + cc * 8;
                float v0, v1;
                if (TOKEN) {
                    float x0 = h[ak * 34 + am];
                    float x1 = h[(ak + 1) * 34 + am];
                    float gm = g[am], bm = bb[am];
                    v0 = (x0 - st[ak]) * st[32 + ak] * gm + bm;
                    v1 = (x1 - st[ak + 1]) * st[32 + ak + 1] * gm + bm;
                } else {
                    float2 x = *reinterpret_cast<const float2*>(h + am * 34 + ak);
                    float mm = st[am], ri = st[32 + am];
                    v0 = (x.x - mm) * ri * g[ak] + bb[ak];
                    v1 = (x.y - mm) * ri * g[ak + 1] + bb[ak + 1];
                }
                __half2 hv = __floats2half2_rn(v0, v1);
                a1[mt][kt][rr + cc * 2] = *reinterpret_cast<unsigned*>(&hv);
            }
        }
    }

    float outacc[2][4][4];
    #pragma unroll
    for (int ntO = 0; ntO < 4; ntO++) {
        int c = ntO * 8 + tg * 2;
        float bv0 = b2[c], bv1 = b2[c + 1];
        #pragma unroll
        for (int mt = 0; mt < 2; mt++) {
            outacc[mt][ntO][0] = bv0; outacc[mt][ntO][1] = bv1;
            outacc[mt][ntO][2] = bv0; outacc[mt][ntO][3] = bv1;
        }
    }

    // base pointers with lane-dependent parts factored once
    const __half* w1b = w1 + gid * 32 + tg * 8;           // + n*32 (imm per nt/nc)
    const __half* w2b = w2 + gid * 288 + tg * 8;          // + ntO*8*288 + (nc*2+j)*32
    const float*  b1b = b1 + tg * 2;                      // + imm

    // ---- hidden loop over DIM=256, FULLY UNROLLED (4 chunks of 64) ----
    #pragma unroll
    for (int nc = 0; nc < 4; nc++) {
        float dAcc[2][8][4];
        #pragma unroll
        for (int nt = 0; nt < 8; nt++) {
            float2 bv = *reinterpret_cast<const float2*>(b1b + nc * 64 + nt * 8);
            #pragma unroll
            for (int mt = 0; mt < 2; mt++) {
                dAcc[mt][nt][0] = bv.x; dAcc[mt][nt][1] = bv.y;
                dAcc[mt][nt][2] = bv.x; dAcc[mt][nt][3] = bv.y;
            }
        }

        #pragma unroll
        for (int nt = 0; nt < 8; nt++) {
            uint4 f = *reinterpret_cast<const uint4*>(
                w1b + (nc * 64 + nt * 8) * 32);
            mma16816(dAcc[0][nt], a1[0][0], f.x, f.y);
            mma16816(dAcc[1][nt], a1[1][0], f.x, f.y);
            mma16816(dAcc[0][nt], a1[0][1], f.z, f.w);
            mma16816(dAcc[1][nt], a1[1][1], f.z, f.w);
        }

        #pragma unroll
        for (int j = 0; j < 2; j++) {
            uint4 fw[4];
            #pragma unroll
            for (int ntO = 0; ntO < 4; ntO++) {
                fw[ntO] = *reinterpret_cast<const uint4*>(
                    w2b + ntO * 8 * 288 + (nc * 2 + j) * 32);
            }
            #pragma unroll
            for (int p = 0; p < 2; p++) {
                int kt2 = 2 * j + p;
                unsigned a2[2][4];
                #pragma unroll
                for (int part = 0; part < 2; part++) {
                    int nt = 2 * kt2 + part;
                    #pragma unroll
                    for (int mt = 0; mt < 2; mt++) {
                        __half2 ha = __floats2half2_rn(dAcc[mt][nt][0],
                                                       dAcc[mt][nt][1]);
                        __half2 hb = __floats2half2_rn(dAcc[mt][nt][2],
                                                       dAcc[mt][nt][3]);
                        __half2 ra = hswish2(ha);
                        __half2 rb = hswish2(hb);
                        a2[mt][part * 2 + 0] = *reinterpret_cast<unsigned*>(&ra);
                        a2[mt][part * 2 + 1] = *reinterpret_cast<unsigned*>(&rb);
                    }
                }
                #pragma unroll
                for (int ntO = 0; ntO < 4; ntO++) {
                    unsigned b0 = p ? fw[ntO].z : fw[ntO].x;
                    unsigned b1r = p ? fw[ntO].w : fw[ntO].y;
                    mma16816(outacc[0][ntO], a2[0], b0, b1r);
                    mma16816(outacc[1][ntO], a2[1], b0, b1r);
                }
            }
        }
    }

    if (TOKEN) {
        #pragma unroll
        for (int mt = 0; mt < 2; mt++)
        #pragma unroll
        for (int ntO = 0; ntO < 4; ntO++) {
            int mm = mt * 16 + gid;
            int nn = ntO * 8 + tg * 2;
            h[nn * 34 + mm]           += outacc[mt][ntO][0];
            h[(nn + 1) * 34 + mm]     += outacc[mt][ntO][1];
            h[nn * 34 + mm + 8]       += outacc[mt][ntO][2];
            h[(nn + 1) * 34 + mm + 8] += outacc[mt][ntO][3];
        }
    } else {
        #pragma unroll
        for (int mt = 0; mt < 2; mt++)
        #pragma unroll
        for (int ntO = 0; ntO < 4; ntO++) {
            int rr0 = mt * 16 + gid;
            int c = ntO * 8 + tg * 2;
            float2* p0 = reinterpret_cast<float2*>(h + rr0 * 34 + c);
            float2 v0 = *p0;
            v0.x += outacc[mt][ntO][0]; v0.y += outacc[mt][ntO][1];
            *p0 = v0;
            float2* p1 = reinterpret_cast<float2*>(h + (rr0 + 8) * 34 + c);
            float2 v1 = *p1;
            v1.x += outacc[mt][ntO][2]; v1.y += outacc[mt][ntO][3];
            *p1 = v1;
        }
    }
    __syncwarp();
}

extern __shared__ char smem_raw[];

__global__ __launch_bounds__(NTHREADS, 2)
void mixer_kernel(
    const float* __restrict__ x,
    const float* __restrict__ conv_w, const float* __restrict__ conv_b,
    const float* __restrict__ fc0_w,  const float* __restrict__ fc0_b,
    const float* __restrict__ ln1_g,  const float* __restrict__ ln1_b,
    const float* __restrict__ b11,    const float* __restrict__ b12,
    const float* __restrict__ ln2_g,  const float* __restrict__ ln2_b,
    const float* __restrict__ b21,    const float* __restrict__ b22,
    const float* __restrict__ fc1_w,  const float* __restrict__ fc1_b,
    const float* __restrict__ fcout_w,const float* __restrict__ fcout_b,
    float* __restrict__ out, int B)
{
    const int tid = threadIdx.x;
    const int lane = tid & 31;
    const int wid = tid >> 5;

    float* sH   = reinterpret_cast<float*>(smem_raw + OFF_H);
    float* sSt  = reinterpret_cast<float*>(smem_raw + OFF_ST);
    float* sB1t = reinterpret_cast<float*>(smem_raw + OFF_B1T);
    float* sB1c = reinterpret_cast<float*>(smem_raw + OFF_B1C);
    float* sB2t = reinterpret_cast<float*>(smem_raw + OFF_B2T);
    float* sB2c = reinterpret_cast<float*>(smem_raw + OFF_B2C);
    float* sL1g = reinterpret_cast<float*>(smem_raw + OFF_LN1G);
    float* sL1b = reinterpret_cast<float*>(smem_raw + OFF_LN1B);
    float* sL2g = reinterpret_cast<float*>(smem_raw + OFF_LN2G);
    float* sL2b = reinterpret_cast<float*>(smem_raw + OFF_LN2B);
    __half* w1t = reinterpret_cast<__half*>(smem_raw + OFF_W1T);
    __half* w1c = reinterpret_cast<__half*>(smem_raw + OFF_W1C);
    __half* w2t = reinterpret_cast<__half*>(smem_raw + OFF_W2T);
    __half* w2c = reinterpret_cast<__half*>(smem_raw + OFF_W2C);
    float* sFw = reinterpret_cast<float*>(smem_raw + OFF_WT);
    float* sFo = reinterpret_cast<float*>(smem_raw + OFF_W1C);

    const int eb = blockIdx.x * NWARPS + wid;
    const bool act = (eb < B);
    float* h  = sH + wid * (32 * 34);
    float* st = sSt + wid * 64;

    // ---- stage fc0 weights, preprocess (conv1x1 + fc0) ----
    for (int i = tid; i < 1024; i += NTHREADS) sFw[i] = fc0_w[i];
    if (tid < 32) sB1t[tid] = fc0_b[tid];
    __syncthreads();

    if (act) {
        const float cw0 = conv_w[0], cw1 = conv_w[1], cw2 = conv_w[2];
        const float cb  = conv_b[0];
        const float* xb = x + (size_t)eb * 3072 + lane * 32;
        float2 gp[16];
        #pragma unroll
        for (int qq = 0; qq < 8; qq++) {
            float4 v0 = *reinterpret_cast<const float4*>(xb + qq * 4);
            float4 v1 = *reinterpret_cast<const float4*>(xb + 1024 + qq * 4);
            float4 v2 = *reinterpret_cast<const float4*>(xb + 2048 + qq * 4);
            gp[2 * qq]     = make_float2(cw0 * v0.x + cw1 * v1.x + cw2 * v2.x + cb,
                                         cw0 * v0.y + cw1 * v1.y + cw2 * v2.y + cb);
            gp[2 * qq + 1] = make_float2(cw0 * v0.z + cw1 * v1.z + cw2 * v2.z + cb,
                                         cw0 * v0.w + cw1 * v1.w + cw2 * v2.w + cb);
        }
        for (int j = 0; j < 32; j++) {
            const float4* wq = reinterpret_cast<const float4*>(sFw + j * 32);
            float2 acc = make_float2(0.f, 0.f), accb = make_float2(0.f, 0.f);
            #pragma unroll
            for (int qq = 0; qq < 8; qq++) {
                float4 w = wq[qq];
                acc  = ffma2(gp[2 * qq],     make_float2(w.x, w.y), acc);
                accb = ffma2(gp[2 * qq + 1], make_float2(w.z, w.w), accb);
            }
            float2 sv = fadd2(acc, accb);
            h[lane * 34 + j] = sv.x + sv.y + sB1t[j];
        }
    }
    __syncthreads();

    // ---- 8 layers x 2 repeats ----
    for (int l = 0; l < 8; l++) {
        {
            const uint4* s1t = reinterpret_cast<const uint4*>(gW1[l][0]);
            const uint4* s1c = reinterpret_cast<const uint4*>(gW1[l][1]);
            uint4* d1t = reinterpret_cast<uint4*>(w1t);
            uint4* d1c = reinterpret_cast<uint4*>(w1c);
            #pragma unroll
            for (int i = tid; i < 1024; i += NTHREADS) {
                d1t[i] = s1t[i];
                d1c[i] = s1c[i];
            }
            const uint4* s2t = reinterpret_cast<const uint4*>(gW2[l][0]);
            const uint4* s2c = reinterpret_cast<const uint4*>(gW2[l][1]);
            uint4* d2t = reinterpret_cast<uint4*>(w2t);
            uint4* d2c = reinterpret_cast<uint4*>(w2c);
            #pragma unroll
            for (int i = tid; i < 1152; i += NTHREADS) {
                d2t[i] = s2t[i];
                d2c[i] = s2c[i];
            }
            if (tid < 256) { sB1t[tid] = b11[l * 256 + tid]; sB1c[tid] = b21[l * 256 + tid]; }
            if (tid < 32) {
                sB2t[tid] = b12[l * 32 + tid];
                sB2c[tid] = b22[l * 32 + tid];
                sL1g[tid] = ln1_g[l * 32 + tid];
                sL1b[tid] = ln1_b[l * 32 + tid];
                sL2g[tid] = ln2_g[l * 32 + tid];
                sL2b[tid] = ln2_b[l * 32 + tid];
            }
        }
        __syncthreads();

        if (act) {
            for (int rep = 0; rep < 2; rep++) {
                mix_branch_mma<true >(h, st, w1t, w2t, sB1t, sB2t, sL1g, sL1b, lane);
                mix_branch_mma<false>(h, st, w1c, w2c, sB1c, sB2c, sL2g, sL2b, lane);
            }
        }
        __syncthreads();
    }

    // ---- head: fc1 + hardswish + avgpool(32) + fcout ----
    {
        const float4* s1 = reinterpret_cast<const float4*>(fc1_w);
        float4* d1 = reinterpret_cast<float4*>(sFw);
        for (int i = tid; i < 1024; i += NTHREADS) d1[i] = s1[i];
        for (int i = tid; i < 1280; i += NTHREADS) sFo[i] = fcout_w[i];
        if (tid < 128) sB1t[tid] = fc1_b[tid];
        if (tid < 10)  sB2t[tid] = fcout_b[tid];
    }
    __syncthreads();

    if (act) {
        float2 ap[16];
        #pragma unroll
        for (int t = 0; t < 16; t++)
            ap[t] = *reinterpret_cast<const float2*>(h + lane * 34 + 2 * t);
        float pool[4] = {0.f, 0.f, 0.f, 0.f};
        for (int d = 0; d < 128; d++) {
            const float4* wq = reinterpret_cast<const float4*>(sFw + d * 32);
            float2 acc = make_float2(0.f, 0.f), accb = make_float2(0.f, 0.f);
            #pragma unroll
            for (int qq = 0; qq < 8; qq++) {
                float4 w = wq[qq];
                acc  = ffma2(ap[2 * qq],     make_float2(w.x, w.y), acc);
                accb = ffma2(ap[2 * qq + 1], make_float2(w.z, w.w), accb);
            }
            float2 sv = fadd2(acc, accb);
            float v = sv.x + sv.y + sB1t[d];
            float y = v * fminf(fmaxf(v + 3.0f, 0.0f), 6.0f) * (1.0f / 6.0f);
            pool[d >> 5] += y;
        }
        #pragma unroll
        for (int p = 0; p < 4; p++) pool[p] *= (1.0f / 32.0f);
        #pragma unroll
        for (int o = 0; o < 10; o++) {
            float4 wv = *reinterpret_cast<const float4*>(sFo + o * 128 + lane * 4);
            float v = pool[0] * wv.x + pool[1] * wv.y + pool[2] * wv.z + pool[3] * wv.w;
            #pragma unroll
            for (int sft = 16; sft > 0; sft >>= 1)
                v += __shfl_xor_sync(0xffffffffu, v, sft);
            if (lane == 0) out[(size_t)eb * 10 + o] = v + sB2t[o];
        }
    }
}

extern "C" void kernel_launch(void* const* d_in, const int* in_sizes, int n_in,
                              void* d_out, int out_size) {
    const float* x       = (const float*)d_in[0];
    const float* conv_w  = (const float*)d_in[1];
    const float* conv_b  = (const float*)d_in[2];
    const float* fc0_w   = (const float*)d_in[3];
    const float* fc0_b   = (const float*)d_in[4];
    const float* ln1_g   = (const float*)d_in[5];
    const float* ln1_b   = (const float*)d_in[6];
    const float* w11     = (const float*)d_in[7];
    const float* b11     = (const float*)d_in[8];
    const float* w12     = (const float*)d_in[9];
    const float* b12     = (const float*)d_in[10];
    const float* ln2_g   = (const float*)d_in[11];
    const float* ln2_b   = (const float*)d_in[12];
    const float* w21     = (const float*)d_in[13];
    const float* b21     = (const float*)d_in[14];
    const float* w22     = (const float*)d_in[15];
    const float* b22     = (const float*)d_in[16];
    const float* fc1_w   = (const float*)d_in[17];
    const float* fc1_b   = (const float*)d_in[18];
    const float* fcout_w = (const float*)d_in[19];
    const float* fcout_b = (const float*)d_in[20];
    float* out = (float*)d_out;

    const int B = in_sizes[0] / 3072;
    const int blocks = (B + NWARPS - 1) / NWARPS;

    prep_weights<<<8, 256>>>(w11, w21, w12, w22);

    cudaFuncSetAttribute(mixer_kernel,
                         cudaFuncAttributeMaxDynamicSharedMemorySize,
                         SMEM_BYTES);
    mixer_kernel<<<blocks, NTHREADS, SMEM_BYTES>>>(
        x, conv_w, conv_b, fc0_w, fc0_b, ln1_g, ln1_b,
        b11, b12, ln2_g, ln2_b, b21, b22,
        fc1_w, fc1_b, fcout_w, fcout_b, out, B);
}